// round 1
// baseline (speedup 1.0000x reference)
#include <cuda_runtime.h>
#include <math.h>

#define NTOK 2048
#define TSEQ 1024
#define D    768
#define FFN  3072
#define NS   6
#define VOC  32000

// ---------------- scratch (static device memory; no allocs) ----------------
#define ROW (NTOK*D)
#define OFF_H     0
#define OFF_MU    (1*ROW)
#define OFF_LAM   (2*ROW)
#define OFF_MUHAT (3*ROW)
#define OFF_MUN   (4*ROW)
#define OFF_MUR   (5*ROW)
#define OFF_SO    (6*ROW)
#define OFF_Q     (7*ROW)
#define OFF_K     (8*ROW)
#define OFF_V     (9*ROW)
#define OFF_MSG   (10*ROW)
#define OFF_DLAM  (11*ROW)
#define OFF_MHAT  (12*ROW)
#define OFF_FIN   (13*ROW)
#define OFF_TRH   (14*ROW)
#define OFF_HB    (14*ROW + NTOK*1536)
#define OFF_PI    (14*ROW + NTOK*1536 + NTOK*FFN)
#define SCRATCH_FLOATS (14*ROW + NTOK*1536 + NTOK*FFN + NTOK*NS)

__device__ float g_scratch[SCRATCH_FLOATS];

// ---------------- device helpers ----------------
__device__ __forceinline__ float gelu_f(float x) {
    // JAX default gelu (approximate=True, tanh form)
    float x3 = x * x * x;
    return 0.5f * x * (1.f + tanhf(0.7978845608028654f * (x + 0.044715f * x3)));
}
__device__ __forceinline__ float softplus_f(float x) {
    // logaddexp(x, 0)
    return fmaxf(x, 0.f) + log1pf(expf(-fabsf(x)));
}

// block-wide sum; red must be shared float[8]; safe for repeated calls
__device__ __forceinline__ float block_sum(float v, float* red) {
    int tid = threadIdx.x;
    __syncthreads();
#pragma unroll
    for (int o = 16; o > 0; o >>= 1) v += __shfl_xor_sync(0xffffffffu, v, o);
    if ((tid & 31) == 0) red[tid >> 5] = v;
    __syncthreads();
    if (tid < 32) {
        float t = (tid < (int)(blockDim.x >> 5)) ? red[tid] : 0.f;
#pragma unroll
        for (int o = 4; o > 0; o >>= 1) t += __shfl_xor_sync(0xffffffffu, t, o);
        if (tid == 0) red[0] = t;
    }
    __syncthreads();
    return red[0];
}

// ---------------- SGEMM: C[M,N] = epi(A[M,K] @ B[K,N]) ----------------
// 128x128 tile, BK=16, 256 threads, 8x8 per thread. All M,N multiples of 128,
// K multiples of 16 in every call site (verified against problem shapes).
enum { EPI_NONE = 0, EPI_BIAS = 1, EPI_GELU = 2, EPI_PIACC = 3, EPI_GSP = 4,
       EPI_SCALE = 5, EPI_SP01 = 6 };

template <int EPI, bool TB>
__global__ void __launch_bounds__(256, 2) sgemm_k(
    const float* __restrict__ A, const float* __restrict__ B,
    const float* __restrict__ bias, float* __restrict__ C,
    int M, int N, int K,
    const float* __restrict__ pi, int piIdx, float alpha)
{
    __shared__ float As[16][128];
    __shared__ float Bs[16][128];
    const int tid = threadIdx.x;
    const int bm0 = blockIdx.y * 128;
    const int bn0 = blockIdx.x * 128;
    const int tx = tid & 15, ty = tid >> 4;

    float c[8][8];
#pragma unroll
    for (int i = 0; i < 8; i++)
#pragma unroll
        for (int j = 0; j < 8; j++) c[i][j] = 0.f;

    for (int k0 = 0; k0 < K; k0 += 16) {
        // A tile: As[kc][row]
#pragma unroll
        for (int it = 0; it < 2; it++) {
            int idx = tid + 256 * it;          // 0..511 float4s
            int row = idx >> 2, q = idx & 3;
            float4 va = *(const float4*)(A + (long)(bm0 + row) * K + k0 + q * 4);
            As[q * 4 + 0][row] = va.x;
            As[q * 4 + 1][row] = va.y;
            As[q * 4 + 2][row] = va.z;
            As[q * 4 + 3][row] = va.w;
        }
        // B tile: Bs[kc][nc]
#pragma unroll
        for (int it = 0; it < 2; it++) {
            int idx = tid + 256 * it;
            if (!TB) {
                int kr = idx >> 5, n4 = idx & 31;
                float4 vb = *(const float4*)(B + (long)(k0 + kr) * N + bn0 + n4 * 4);
                *(float4*)(&Bs[kr][n4 * 4]) = vb;
            } else {
                int nc = idx >> 2, q = idx & 3;
                float4 vb = *(const float4*)(B + (long)(bn0 + nc) * K + k0 + q * 4);
                Bs[q * 4 + 0][nc] = vb.x;
                Bs[q * 4 + 1][nc] = vb.y;
                Bs[q * 4 + 2][nc] = vb.z;
                Bs[q * 4 + 3][nc] = vb.w;
            }
        }
        __syncthreads();
#pragma unroll
        for (int kk = 0; kk < 16; kk++) {
            float a[8], b[8];
#pragma unroll
            for (int i = 0; i < 8; i++) a[i] = As[kk][ty * 8 + i];
#pragma unroll
            for (int j = 0; j < 8; j++) b[j] = Bs[kk][tx * 8 + j];
#pragma unroll
            for (int i = 0; i < 8; i++)
#pragma unroll
                for (int j = 0; j < 8; j++) c[i][j] += a[i] * b[j];
        }
        __syncthreads();
    }

    const int col0 = bn0 + tx * 8;
    float bb[8];
    if (EPI == EPI_BIAS || EPI == EPI_GELU || EPI == EPI_PIACC ||
        EPI == EPI_GSP || EPI == EPI_SP01) {
#pragma unroll
        for (int j = 0; j < 8; j++) bb[j] = bias[col0 + j];
    }
#pragma unroll
    for (int i = 0; i < 8; i++) {
        int row = bm0 + ty * 8 + i;
        float rs = 0.f;
        if (EPI == EPI_PIACC || EPI == EPI_GSP) rs = pi[row * NS + piIdx];
        float* cp = C + (long)row * N + col0;
#pragma unroll
        for (int j = 0; j < 8; j++) {
            float v = c[i][j];
            if (EPI == EPI_BIAS)       v = v + bb[j];
            else if (EPI == EPI_GELU)  v = gelu_f(v + bb[j]);
            else if (EPI == EPI_PIACC) v = cp[j] + rs * (v + bb[j]);
            else if (EPI == EPI_GSP)   v = rs * softplus_f(v + bb[j]);
            else if (EPI == EPI_SCALE) v = v * alpha;
            else if (EPI == EPI_SP01)  v = softplus_f(v + bb[j]) + 0.1f;
            cp[j] = v;
        }
    }
}

// ---------------- small kernels ----------------
__global__ void emb_k(const int* __restrict__ x, const float* __restrict__ emb,
                      const float* __restrict__ pos, float* __restrict__ h)
{
    int n = blockIdx.x;
    int vx = x[n];
    int t = n % TSEQ;
    const float* e = emb + (long)vx * D;
    const float* p = pos + (long)t * D;
    for (int j = threadIdx.x; j < D; j += blockDim.x)
        h[(long)n * D + j] = e[j] + p[j];
}

__global__ void pi_init_k(float* __restrict__ pi)
{
    int i = blockIdx.x * blockDim.x + threadIdx.x;
    if (i < NTOK * NS) pi[i] = ((i % NS) == 2) ? 1.f : 0.f;
}

__global__ void zero_k(float* __restrict__ p, int n)
{
    int i = blockIdx.x * blockDim.x + threadIdx.x;
    if (i < n) p[i] = 0.f;
}

// ln(mu,0)->mun, ln(mu,2)->mur, normalized core -> muhat
__global__ void ln012_k(const float* __restrict__ mu, float* __restrict__ muhat,
                        float* __restrict__ mun, float* __restrict__ mur,
                        const float* __restrict__ ln_g, const float* __restrict__ ln_b)
{
    __shared__ float red[8];
    int n = blockIdx.x, tid = threadIdx.x; // 256
    const float* row = mu + (long)n * D;
    float v[3], s = 0.f;
#pragma unroll
    for (int r = 0; r < 3; r++) { v[r] = row[tid + r * 256]; s += v[r]; }
    float mean = block_sum(s, red) / D;
    float qv = 0.f;
#pragma unroll
    for (int r = 0; r < 3; r++) { float d = v[r] - mean; qv += d * d; }
    float var = block_sum(qv, red) / D;
    float inv = rsqrtf(var + 1e-5f);
#pragma unroll
    for (int r = 0; r < 3; r++) {
        int j = tid + r * 256;
        float nh = (v[r] - mean) * inv;
        long idx = (long)n * D + j;
        muhat[idx] = nh;
        mun[idx] = nh * ln_g[j] + ln_b[j];
        mur[idx] = nh * ln_g[2 * D + j] + ln_b[2 * D + j];
    }
}

__global__ void ln_gen_k(const float* __restrict__ in, float* __restrict__ out,
                         const float* __restrict__ g, const float* __restrict__ b)
{
    __shared__ float red[8];
    int n = blockIdx.x, tid = threadIdx.x; // 256
    const float* row = in + (long)n * D;
    float v[3], s = 0.f;
#pragma unroll
    for (int r = 0; r < 3; r++) { v[r] = row[tid + r * 256]; s += v[r]; }
    float mean = block_sum(s, red) / D;
    float qv = 0.f;
#pragma unroll
    for (int r = 0; r < 3; r++) { float d = v[r] - mean; qv += d * d; }
    float var = block_sum(qv, red) / D;
    float inv = rsqrtf(var + 1e-5f);
#pragma unroll
    for (int r = 0; r < 3; r++) {
        int j = tid + r * 256;
        out[(long)n * D + j] = (v[r] - mean) * inv * g[j] + b[j];
    }
}

// kz -> K softmax -> pi_ev; ev; pi_new; top-2 mask; renorm; pi updated in-place
__global__ void routing_k(const float* __restrict__ trh, const float* __restrict__ w2,
                          const float* __restrict__ b2, const float* __restrict__ mun,
                          const float* __restrict__ evw, const float* __restrict__ evb,
                          float* __restrict__ pi)
{
    __shared__ float sh[1536];
    __shared__ float sm[D];
    __shared__ float kz[36];
    __shared__ float ev[6];
    __shared__ float spi[6];
    int n = blockIdx.x, tid = threadIdx.x; // 128
    for (int i = tid; i < 1536; i += 128) sh[i] = trh[(long)n * 1536 + i];
    for (int i = tid; i < D; i += 128)    sm[i] = mun[(long)n * D + i];
    if (tid < NS) spi[tid] = pi[n * NS + tid];
    __syncthreads();
    if (tid < 36) {
        float acc = b2[tid];
        for (int k = 0; k < 1536; k++) acc += sh[k] * w2[k * 36 + tid];
        kz[tid] = acc;
    } else if (tid < 42) {
        int j = tid - 36;
        float acc = evb[j];
        for (int k = 0; k < D; k++) acc += sm[k] * evw[k * NS + j];
        ev[j] = acc;
    }
    __syncthreads();
    if (tid == 0) {
        float Kr[6][6];
        for (int s = 0; s < 6; s++) {
            float mx = kz[s * 6];
            for (int u = 1; u < 6; u++) mx = fmaxf(mx, kz[s * 6 + u]);
            float sum = 0.f;
            for (int u = 0; u < 6; u++) { float e = expf(kz[s * 6 + u] - mx); Kr[s][u] = e; sum += e; }
            float invr = 1.f / sum;
            for (int u = 0; u < 6; u++) Kr[s][u] *= invr;
        }
        float pev[6];
        for (int u = 0; u < 6; u++) {
            float a = 0.f;
            for (int s = 0; s < 6; s++) a += spi[s] * Kr[s][u];
            pev[u] = a;
        }
        float mx = ev[0] * 2.f;
        for (int u = 1; u < 6; u++) mx = fmaxf(mx, ev[u] * 2.f);
        float wv[6], sw = 0.f;
        for (int u = 0; u < 6; u++) { wv[u] = expf(ev[u] * 2.f - mx); sw += wv[u]; }
        float invw = 1.f / sw;
        float pn[6], s1 = 0.f;
        for (int u = 0; u < 6; u++) { pn[u] = pev[u] * wv[u] * invw; s1 += pn[u]; }
        float inv1 = 1.f / fmaxf(s1, 1e-8f);
        for (int u = 0; u < 6; u++) pn[u] *= inv1;
        int i1 = 0;
        for (int u = 1; u < 6; u++) if (pn[u] > pn[i1]) i1 = u;
        int i2 = (i1 == 0) ? 1 : 0;
        for (int u = 0; u < 6; u++) if (u != i1 && pn[u] > pn[i2]) i2 = u;
        float inv2 = 1.f / fmaxf(pn[i1] + pn[i2], 1e-8f);
        for (int u = 0; u < 6; u++)
            pi[n * NS + u] = (u == i1 || u == i2) ? pn[u] * inv2 : 0.f;
    }
}

// 4-offset local attention + pi3 gate + ln3 -> msg
__global__ void attn_k(const float* __restrict__ q, const float* __restrict__ k,
                       const float* __restrict__ v, const float* __restrict__ pi,
                       const float* __restrict__ ln_g, const float* __restrict__ ln_b,
                       float* __restrict__ msg)
{
    __shared__ float sw[4];
    __shared__ float mb[D];
    __shared__ float red[8];
    int n = blockIdx.x, tid = threadIdx.x; // 128
    int t = n % TSEQ;
    int warp = tid >> 5, lane = tid & 31;
    const int offs[4] = {-2, -1, 1, 2};
    {
        int o = offs[warp];
        int tt = t + o;
        float dot = 0.f;
        if (tt >= 0 && tt < TSEQ) {
            const float* qp = q + (long)n * D;
            const float* kp = k + (long)(n + o) * D;
            for (int j = lane; j < D; j += 32) dot += qp[j] * kp[j];
        }
#pragma unroll
        for (int s = 16; s > 0; s >>= 1) dot += __shfl_xor_sync(0xffffffffu, dot, s);
        if (lane == 0)
            sw[warp] = (tt >= 0 && tt < TSEQ) ? dot / 27.712812921102035f : -1e9f;
    }
    __syncthreads();
    float w0 = sw[0], w1 = sw[1], w2 = sw[2], w3 = sw[3];
    float mx = fmaxf(fmaxf(w0, w1), fmaxf(w2, w3));
    float wt[4] = {expf(w0 - mx), expf(w1 - mx), expf(w2 - mx), expf(w3 - mx)};
    float invs = 1.f / (wt[0] + wt[1] + wt[2] + wt[3]);
#pragma unroll
    for (int w = 0; w < 4; w++) wt[w] *= invs;
    float pi3 = pi[n * NS + 3];
    for (int j = tid; j < D; j += 128) {
        float m = 0.f;
#pragma unroll
        for (int w = 0; w < 4; w++) {
            int tt = t + offs[w];
            if (tt >= 0 && tt < TSEQ) m += wt[w] * v[(long)(n + offs[w]) * D + j];
        }
        mb[j] = m * pi3;
    }
    __syncthreads();
    float loc[6], s = 0.f;
#pragma unroll
    for (int r = 0; r < 6; r++) { loc[r] = mb[tid + r * 128]; s += loc[r]; }
    float mean = block_sum(s, red) / D;
    float qv = 0.f;
#pragma unroll
    for (int r = 0; r < 6; r++) { float d = loc[r] - mean; qv += d * d; }
    float var = block_sum(qv, red) / D;
    float inv = rsqrtf(var + 1e-5f);
#pragma unroll
    for (int r = 0; r < 6; r++) {
        int j = tid + r * 128;
        msg[(long)n * D + j] = (loc[r] - mean) * inv * ln_g[3 * D + j] + ln_b[3 * D + j];
    }
}

// mu=(lam*ln4(mu) + dlam*m_hat)/(lam+dlam); lam+=dlam; mu=ln5(mu)+so*0.1
__global__ void update_k(const float* __restrict__ muhat, float* __restrict__ lam,
                         const float* __restrict__ dlam, const float* __restrict__ mhat,
                         const float* __restrict__ so,
                         const float* __restrict__ ln_g, const float* __restrict__ ln_b,
                         float* __restrict__ mu)
{
    __shared__ float red[8];
    int n = blockIdx.x, tid = threadIdx.x; // 256
    float mval[3], s = 0.f;
#pragma unroll
    for (int r = 0; r < 3; r++) {
        int j = tid + r * 256;
        long idx = (long)n * D + j;
        float l = lam[idx], dl = dlam[idx];
        float mwn = muhat[idx] * ln_g[4 * D + j] + ln_b[4 * D + j];
        float lnw = l + dl;
        float m = (l * mwn + dl * mhat[idx]) / lnw;
        lam[idx] = lnw;
        mval[r] = m;
        s += m;
    }
    float mean = block_sum(s, red) / D;
    float qv = 0.f;
#pragma unroll
    for (int r = 0; r < 3; r++) { float d = mval[r] - mean; qv += d * d; }
    float var = block_sum(qv, red) / D;
    float inv = rsqrtf(var + 1e-5f);
#pragma unroll
    for (int r = 0; r < 3; r++) {
        int j = tid + r * 256;
        long idx = (long)n * D + j;
        mu[idx] = (mval[r] - mean) * inv * ln_g[5 * D + j] + ln_b[5 * D + j] + so[idx] * 0.1f;
    }
}

// ---------------- launcher ----------------
extern "C" void kernel_launch(void* const* d_in, const int* in_sizes, int n_in,
                              void* d_out, int out_size)
{
    const int*   x        = (const int*)d_in[0];
    const float* emb_w    = (const float*)d_in[1];
    const float* pos_w    = (const float*)d_in[2];
    const float* mu_w     = (const float*)d_in[3];
    const float* mu_b     = (const float*)d_in[4];
    const float* lam_w    = (const float*)d_in[5];
    const float* lam_b    = (const float*)d_in[6];
    const float* tr_w1    = (const float*)d_in[7];
    const float* tr_b1    = (const float*)d_in[8];
    const float* tr_w2    = (const float*)d_in[9];
    const float* tr_b2    = (const float*)d_in[10];
    const float* bank_w1  = (const float*)d_in[11];
    const float* bank_b1  = (const float*)d_in[12];
    const float* bank_w2  = (const float*)d_in[13];
    const float* bank_b2  = (const float*)d_in[14];
    const float* ev_w     = (const float*)d_in[15];
    const float* ev_b     = (const float*)d_in[16];
    const float* rt_q     = (const float*)d_in[17];
    const float* rt_k     = (const float*)d_in[18];
    const float* rt_v     = (const float*)d_in[19];
    const float* wr_lam_w = (const float*)d_in[20];
    const float* wr_lam_b = (const float*)d_in[21];
    const float* wr_mu_w  = (const float*)d_in[22];
    const float* wr_mu_b  = (const float*)d_in[23];
    const float* ln_g     = (const float*)d_in[24];
    const float* ln_b     = (const float*)d_in[25];
    float* out = (float*)d_out;

    float* base = nullptr;
    cudaGetSymbolAddress((void**)&base, g_scratch);
    float* h     = base + OFF_H;
    float* mu    = base + OFF_MU;
    float* lam   = base + OFF_LAM;
    float* muhat = base + OFF_MUHAT;
    float* mun   = base + OFF_MUN;
    float* mur   = base + OFF_MUR;
    float* so    = base + OFF_SO;
    float* qb    = base + OFF_Q;
    float* kb    = base + OFF_K;
    float* vb    = base + OFF_V;
    float* msg   = base + OFF_MSG;
    float* dlam  = base + OFF_DLAM;
    float* mhat  = base + OFF_MHAT;
    float* fin   = base + OFF_FIN;
    float* trh   = base + OFF_TRH;
    float* hb    = base + OFF_HB;
    float* pi    = base + OFF_PI;

    const float inv_sqrt_d = 0.03608439182435161f; // 1/sqrt(768)

    emb_k<<<NTOK, 256>>>(x, emb_w, pos_w, h);
    {
        dim3 g(D / 128, NTOK / 128);
        sgemm_k<EPI_BIAS, false><<<g, 256>>>(h, mu_w, mu_b, mu, NTOK, D, D, nullptr, 0, 1.f);
        sgemm_k<EPI_SP01, false><<<g, 256>>>(h, lam_w, lam_b, lam, NTOK, D, D, nullptr, 0, 1.f);
    }
    pi_init_k<<<(NTOK * NS + 255) / 256, 256>>>(pi);

    for (int step = 0; step < 3; step++) {
        ln012_k<<<NTOK, 256>>>(mu, muhat, mun, mur, ln_g, ln_b);
        {
            dim3 g(1536 / 128, NTOK / 128);
            sgemm_k<EPI_GELU, false><<<g, 256>>>(mu, tr_w1, tr_b1, trh, NTOK, 1536, D, nullptr, 0, 1.f);
        }
        zero_k<<<(ROW + 255) / 256, 256>>>(so, ROW);
        for (int s = 0; s < NS; s++) {
            dim3 g1(FFN / 128, NTOK / 128);
            sgemm_k<EPI_GELU, false><<<g1, 256>>>(mun, bank_w1 + (long)s * D * FFN,
                                                  bank_b1 + s * FFN, hb, NTOK, FFN, D,
                                                  nullptr, 0, 1.f);
            dim3 g2(D / 128, NTOK / 128);
            sgemm_k<EPI_PIACC, false><<<g2, 256>>>(hb, bank_w2 + (long)s * FFN * D,
                                                   bank_b2 + s * D, so, NTOK, D, FFN,
                                                   pi, s, 1.f);
        }
        ln_gen_k<<<NTOK, 256>>>(so, so, ln_g + 1 * D, ln_b + 1 * D);
        routing_k<<<NTOK, 128>>>(trh, tr_w2, tr_b2, mun, ev_w, ev_b, pi);
        {
            dim3 g(D / 128, NTOK / 128);
            sgemm_k<EPI_NONE, false><<<g, 256>>>(mur, rt_q, nullptr, qb, NTOK, D, D, nullptr, 0, 1.f);
            sgemm_k<EPI_NONE, false><<<g, 256>>>(mur, rt_k, nullptr, kb, NTOK, D, D, nullptr, 0, 1.f);
            sgemm_k<EPI_NONE, false><<<g, 256>>>(mur, rt_v, nullptr, vb, NTOK, D, D, nullptr, 0, 1.f);
        }
        attn_k<<<NTOK, 128>>>(qb, kb, vb, pi, ln_g, ln_b, msg);
        {
            dim3 g(D / 128, NTOK / 128);
            sgemm_k<EPI_GSP, false><<<g, 256>>>(msg, wr_lam_w, wr_lam_b, dlam, NTOK, D, D, pi, 4, 1.f);
            sgemm_k<EPI_BIAS, false><<<g, 256>>>(msg, wr_mu_w, wr_mu_b, mhat, NTOK, D, D, nullptr, 0, 1.f);
        }
        update_k<<<NTOK, 256>>>(muhat, lam, dlam, mhat, so, ln_g, ln_b, mu);
    }

    ln_gen_k<<<NTOK, 256>>>(mu, fin, ln_g + 6 * D, ln_b + 6 * D);
    {
        dim3 g(VOC / 128, NTOK / 128);
        sgemm_k<EPI_SCALE, true><<<g, 256>>>(fin, emb_w, nullptr, out, NTOK, VOC, D,
                                             nullptr, 0, inv_sqrt_d);
    }
}

// round 2
// speedup vs baseline: 1.3379x; 1.3379x over previous
#include <cuda_runtime.h>
#include <math.h>

#define NTOK 2048
#define TSEQ 1024
#define D    768
#define FFN  3072
#define NS   6
#define VOC  32000

// ---------------- scratch (static device memory; no allocs) ----------------
#define ROW (NTOK*D)
#define OFF_H     0
#define OFF_MU    (1*ROW)
#define OFF_LAM   (2*ROW)
#define OFF_MUHAT (3*ROW)
#define OFF_MUN   (4*ROW)
#define OFF_MUR   (5*ROW)
#define OFF_SO    (6*ROW)
#define OFF_Q     (7*ROW)
#define OFF_K     (8*ROW)
#define OFF_V     (9*ROW)
#define OFF_MSG   (10*ROW)
#define OFF_DLAM  (11*ROW)
#define OFF_MHAT  (12*ROW)
#define OFF_FIN   (13*ROW)
#define OFF_TRH   (14*ROW)
#define OFF_HB    (14*ROW + NTOK*1536)
#define OFF_PI    (14*ROW + NTOK*1536 + NTOK*FFN)
#define SCRATCH_FLOATS (14*ROW + NTOK*1536 + NTOK*FFN + NTOK*NS)

__device__ float g_scratch[SCRATCH_FLOATS];
__device__ int   g_cnt[NS];
__device__ int   g_list[NS * NTOK];

// ---------------- device helpers ----------------
__device__ __forceinline__ float gelu_f(float x) {
    float x3 = x * x * x;
    return 0.5f * x * (1.f + tanhf(0.7978845608028654f * (x + 0.044715f * x3)));
}
__device__ __forceinline__ float softplus_f(float x) {
    return fmaxf(x, 0.f) + log1pf(expf(-fabsf(x)));
}

__device__ __forceinline__ float block_sum(float v, float* red) {
    int tid = threadIdx.x;
    __syncthreads();
#pragma unroll
    for (int o = 16; o > 0; o >>= 1) v += __shfl_xor_sync(0xffffffffu, v, o);
    if ((tid & 31) == 0) red[tid >> 5] = v;
    __syncthreads();
    if (tid < 32) {
        float t = (tid < (int)(blockDim.x >> 5)) ? red[tid] : 0.f;
#pragma unroll
        for (int o = 4; o > 0; o >>= 1) t += __shfl_xor_sync(0xffffffffu, t, o);
        if (tid == 0) red[0] = t;
    }
    __syncthreads();
    return red[0];
}

// ---------------- dense SGEMM ----------------
enum { EPI_NONE = 0, EPI_BIAS = 1, EPI_GELU = 2, EPI_GSP = 4,
       EPI_SCALE = 5, EPI_SP01 = 6 };

template <int EPI, bool TB>
__global__ void __launch_bounds__(256, 2) sgemm_k(
    const float* __restrict__ A, const float* __restrict__ B,
    const float* __restrict__ bias, float* __restrict__ C,
    int M, int N, int K,
    const float* __restrict__ pi, int piIdx, float alpha)
{
    __shared__ float As[16][128];
    __shared__ float Bs[16][128];
    const int tid = threadIdx.x;
    const int bm0 = blockIdx.y * 128;
    const int bn0 = blockIdx.x * 128;
    const int tx = tid & 15, ty = tid >> 4;

    float c[8][8];
#pragma unroll
    for (int i = 0; i < 8; i++)
#pragma unroll
        for (int j = 0; j < 8; j++) c[i][j] = 0.f;

    for (int k0 = 0; k0 < K; k0 += 16) {
#pragma unroll
        for (int it = 0; it < 2; it++) {
            int idx = tid + 256 * it;
            int row = idx >> 2, q = idx & 3;
            float4 va = *(const float4*)(A + (long)(bm0 + row) * K + k0 + q * 4);
            As[q * 4 + 0][row] = va.x;
            As[q * 4 + 1][row] = va.y;
            As[q * 4 + 2][row] = va.z;
            As[q * 4 + 3][row] = va.w;
        }
#pragma unroll
        for (int it = 0; it < 2; it++) {
            int idx = tid + 256 * it;
            if (!TB) {
                int kr = idx >> 5, n4 = idx & 31;
                float4 vb = *(const float4*)(B + (long)(k0 + kr) * N + bn0 + n4 * 4);
                *(float4*)(&Bs[kr][n4 * 4]) = vb;
            } else {
                int nc = idx >> 2, q = idx & 3;
                float4 vb = *(const float4*)(B + (long)(bn0 + nc) * K + k0 + q * 4);
                Bs[q * 4 + 0][nc] = vb.x;
                Bs[q * 4 + 1][nc] = vb.y;
                Bs[q * 4 + 2][nc] = vb.z;
                Bs[q * 4 + 3][nc] = vb.w;
            }
        }
        __syncthreads();
#pragma unroll
        for (int kk = 0; kk < 16; kk++) {
            float a[8], b[8];
#pragma unroll
            for (int i = 0; i < 8; i++) a[i] = As[kk][ty * 8 + i];
#pragma unroll
            for (int j = 0; j < 8; j++) b[j] = Bs[kk][tx * 8 + j];
#pragma unroll
            for (int i = 0; i < 8; i++)
#pragma unroll
                for (int j = 0; j < 8; j++) c[i][j] += a[i] * b[j];
        }
        __syncthreads();
    }

    const int col0 = bn0 + tx * 8;
    float bb[8];
    if (EPI == EPI_BIAS || EPI == EPI_GELU || EPI == EPI_GSP || EPI == EPI_SP01) {
#pragma unroll
        for (int j = 0; j < 8; j++) bb[j] = bias[col0 + j];
    }
#pragma unroll
    for (int i = 0; i < 8; i++) {
        int row = bm0 + ty * 8 + i;
        float rs = 0.f;
        if (EPI == EPI_GSP) rs = pi[row * NS + piIdx];
        float* cp = C + (long)row * N + col0;
#pragma unroll
        for (int j = 0; j < 8; j++) {
            float v = c[i][j];
            if (EPI == EPI_BIAS)       v = v + bb[j];
            else if (EPI == EPI_GELU)  v = gelu_f(v + bb[j]);
            else if (EPI == EPI_GSP)   v = rs * softplus_f(v + bb[j]);
            else if (EPI == EPI_SCALE) v = v * alpha;
            else if (EPI == EPI_SP01)  v = softplus_f(v + bb[j]) + 0.1f;
            cp[j] = v;
        }
    }
}

// ---------------- gathered bank GEMMs (pi-sparse) ----------------
// GEMM1: hb[slot] = gelu(mun[tok] @ W1 + b1), tok = list[slot], slot < cnt
__global__ void __launch_bounds__(256, 2) bank1_gather_k(
    const float* __restrict__ A, const float* __restrict__ B,
    const float* __restrict__ bias, float* __restrict__ C,
    const int* __restrict__ list, const int* __restrict__ cntPtr)
{
    const int cnt = *cntPtr;
    const int bm0 = blockIdx.y * 128;
    if (bm0 >= cnt) return;
    __shared__ float As[16][128];
    __shared__ float Bs[16][128];
    __shared__ int   rowTok[128];
    const int tid = threadIdx.x;
    const int bn0 = blockIdx.x * 128;
    const int tx = tid & 15, ty = tid >> 4;
    if (tid < 128) {
        int r = bm0 + tid;
        rowTok[tid] = list[min(r, cnt - 1)];
    }
    __syncthreads();

    float c[8][8];
#pragma unroll
    for (int i = 0; i < 8; i++)
#pragma unroll
        for (int j = 0; j < 8; j++) c[i][j] = 0.f;

    const int K = D, N = FFN;
    for (int k0 = 0; k0 < K; k0 += 16) {
#pragma unroll
        for (int it = 0; it < 2; it++) {
            int idx = tid + 256 * it;
            int row = idx >> 2, q = idx & 3;
            float4 va = *(const float4*)(A + (long)rowTok[row] * K + k0 + q * 4);
            As[q * 4 + 0][row] = va.x;
            As[q * 4 + 1][row] = va.y;
            As[q * 4 + 2][row] = va.z;
            As[q * 4 + 3][row] = va.w;
        }
#pragma unroll
        for (int it = 0; it < 2; it++) {
            int idx = tid + 256 * it;
            int kr = idx >> 5, n4 = idx & 31;
            float4 vb = *(const float4*)(B + (long)(k0 + kr) * N + bn0 + n4 * 4);
            *(float4*)(&Bs[kr][n4 * 4]) = vb;
        }
        __syncthreads();
#pragma unroll
        for (int kk = 0; kk < 16; kk++) {
            float a[8], b[8];
#pragma unroll
            for (int i = 0; i < 8; i++) a[i] = As[kk][ty * 8 + i];
#pragma unroll
            for (int j = 0; j < 8; j++) b[j] = Bs[kk][tx * 8 + j];
#pragma unroll
            for (int i = 0; i < 8; i++)
#pragma unroll
                for (int j = 0; j < 8; j++) c[i][j] += a[i] * b[j];
        }
        __syncthreads();
    }

    const int col0 = bn0 + tx * 8;
    float bb[8];
#pragma unroll
    for (int j = 0; j < 8; j++) bb[j] = bias[col0 + j];
#pragma unroll
    for (int i = 0; i < 8; i++) {
        int slot = bm0 + ty * 8 + i;
        if (slot >= cnt) continue;
        float* cp = C + (long)slot * N + col0;
#pragma unroll
        for (int j = 0; j < 8; j++) cp[j] = gelu_f(c[i][j] + bb[j]);
    }
}

// GEMM2: so[tok] += pi[tok,s] * (hb[slot] @ W2 + b2)
__global__ void __launch_bounds__(256, 2) bank2_scatter_k(
    const float* __restrict__ A, const float* __restrict__ B,
    const float* __restrict__ bias, float* __restrict__ C,
    const int* __restrict__ list, const int* __restrict__ cntPtr,
    const float* __restrict__ pi, int s)
{
    const int cnt = *cntPtr;
    const int bm0 = blockIdx.y * 128;
    if (bm0 >= cnt) return;
    __shared__ float As[16][128];
    __shared__ float Bs[16][128];
    const int tid = threadIdx.x;
    const int bn0 = blockIdx.x * 128;
    const int tx = tid & 15, ty = tid >> 4;

    float c[8][8];
#pragma unroll
    for (int i = 0; i < 8; i++)
#pragma unroll
        for (int j = 0; j < 8; j++) c[i][j] = 0.f;

    const int K = FFN, N = D;
    for (int k0 = 0; k0 < K; k0 += 16) {
#pragma unroll
        for (int it = 0; it < 2; it++) {
            int idx = tid + 256 * it;
            int row = idx >> 2, q = idx & 3;
            float4 va = *(const float4*)(A + (long)(bm0 + row) * K + k0 + q * 4);
            As[q * 4 + 0][row] = va.x;
            As[q * 4 + 1][row] = va.y;
            As[q * 4 + 2][row] = va.z;
            As[q * 4 + 3][row] = va.w;
        }
#pragma unroll
        for (int it = 0; it < 2; it++) {
            int idx = tid + 256 * it;
            int kr = idx >> 5, n4 = idx & 31;
            float4 vb = *(const float4*)(B + (long)(k0 + kr) * N + bn0 + n4 * 4);
            *(float4*)(&Bs[kr][n4 * 4]) = vb;
        }
        __syncthreads();
#pragma unroll
        for (int kk = 0; kk < 16; kk++) {
            float a[8], b[8];
#pragma unroll
            for (int i = 0; i < 8; i++) a[i] = As[kk][ty * 8 + i];
#pragma unroll
            for (int j = 0; j < 8; j++) b[j] = Bs[kk][tx * 8 + j];
#pragma unroll
            for (int i = 0; i < 8; i++)
#pragma unroll
                for (int j = 0; j < 8; j++) c[i][j] += a[i] * b[j];
        }
        __syncthreads();
    }

    const int col0 = bn0 + tx * 8;
    float bb[8];
#pragma unroll
    for (int j = 0; j < 8; j++) bb[j] = bias[col0 + j];
#pragma unroll
    for (int i = 0; i < 8; i++) {
        int slot = bm0 + ty * 8 + i;
        if (slot >= cnt) continue;
        int tok = list[slot];
        float rs = pi[tok * NS + s];
        float* cp = C + (long)tok * N + col0;
#pragma unroll
        for (int j = 0; j < 8; j++) cp[j] += rs * (c[i][j] + bb[j]);
    }
}

// ---------------- small kernels ----------------
__global__ void emb_k(const int* __restrict__ x, const float* __restrict__ emb,
                      const float* __restrict__ pos, float* __restrict__ h)
{
    int n = blockIdx.x;
    int vx = x[n];
    int t = n % TSEQ;
    const float* e = emb + (long)vx * D;
    const float* p = pos + (long)t * D;
    for (int j = threadIdx.x; j < D; j += blockDim.x)
        h[(long)n * D + j] = e[j] + p[j];
}

__global__ void pi_init_k(float* __restrict__ pi)
{
    int i = blockIdx.x * blockDim.x + threadIdx.x;
    if (i < NTOK * NS) pi[i] = ((i % NS) == 2) ? 1.f : 0.f;
}

__global__ void zero_k(float* __restrict__ p, int n)
{
    int i = blockIdx.x * blockDim.x + threadIdx.x;
    if (i < n) p[i] = 0.f;
}

__global__ void reset_cnt_k(int* cnt)
{
    if (threadIdx.x < NS) cnt[threadIdx.x] = 0;
}

__global__ void build_lists_k(const float* __restrict__ pi,
                              int* __restrict__ cnt, int* __restrict__ list)
{
    int t = blockIdx.x * blockDim.x + threadIdx.x;
    if (t >= NTOK) return;
#pragma unroll
    for (int s = 0; s < NS; s++) {
        if (pi[t * NS + s] != 0.f) {
            int pos = atomicAdd(&cnt[s], 1);
            list[s * NTOK + pos] = t;
        }
    }
}

__global__ void ln012_k(const float* __restrict__ mu, float* __restrict__ muhat,
                        float* __restrict__ mun, float* __restrict__ mur,
                        const float* __restrict__ ln_g, const float* __restrict__ ln_b)
{
    __shared__ float red[8];
    int n = blockIdx.x, tid = threadIdx.x;
    const float* row = mu + (long)n * D;
    float v[3], s = 0.f;
#pragma unroll
    for (int r = 0; r < 3; r++) { v[r] = row[tid + r * 256]; s += v[r]; }
    float mean = block_sum(s, red) / D;
    float qv = 0.f;
#pragma unroll
    for (int r = 0; r < 3; r++) { float d = v[r] - mean; qv += d * d; }
    float var = block_sum(qv, red) / D;
    float inv = rsqrtf(var + 1e-5f);
#pragma unroll
    for (int r = 0; r < 3; r++) {
        int j = tid + r * 256;
        float nh = (v[r] - mean) * inv;
        long idx = (long)n * D + j;
        muhat[idx] = nh;
        mun[idx] = nh * ln_g[j] + ln_b[j];
        mur[idx] = nh * ln_g[2 * D + j] + ln_b[2 * D + j];
    }
}

__global__ void ln_gen_k(const float* __restrict__ in, float* __restrict__ out,
                         const float* __restrict__ g, const float* __restrict__ b)
{
    __shared__ float red[8];
    int n = blockIdx.x, tid = threadIdx.x;
    const float* row = in + (long)n * D;
    float v[3], s = 0.f;
#pragma unroll
    for (int r = 0; r < 3; r++) { v[r] = row[tid + r * 256]; s += v[r]; }
    float mean = block_sum(s, red) / D;
    float qv = 0.f;
#pragma unroll
    for (int r = 0; r < 3; r++) { float d = v[r] - mean; qv += d * d; }
    float var = block_sum(qv, red) / D;
    float inv = rsqrtf(var + 1e-5f);
#pragma unroll
    for (int r = 0; r < 3; r++) {
        int j = tid + r * 256;
        out[(long)n * D + j] = (v[r] - mean) * inv * g[j] + b[j];
    }
}

__global__ void routing_k(const float* __restrict__ trh, const float* __restrict__ w2,
                          const float* __restrict__ b2, const float* __restrict__ mun,
                          const float* __restrict__ evw, const float* __restrict__ evb,
                          float* __restrict__ pi)
{
    __shared__ float sh[1536];
    __shared__ float sm[D];
    __shared__ float kz[36];
    __shared__ float ev[6];
    __shared__ float spi[6];
    int n = blockIdx.x, tid = threadIdx.x;
    for (int i = tid; i < 1536; i += 128) sh[i] = trh[(long)n * 1536 + i];
    for (int i = tid; i < D; i += 128)    sm[i] = mun[(long)n * D + i];
    if (tid < NS) spi[tid] = pi[n * NS + tid];
    __syncthreads();
    if (tid < 36) {
        float acc = b2[tid];
        for (int k = 0; k < 1536; k++) acc += sh[k] * w2[k * 36 + tid];
        kz[tid] = acc;
    } else if (tid < 42) {
        int j = tid - 36;
        float acc = evb[j];
        for (int k = 0; k < D; k++) acc += sm[k] * evw[k * NS + j];
        ev[j] = acc;
    }
    __syncthreads();
    if (tid == 0) {
        float Kr[6][6];
        for (int s = 0; s < 6; s++) {
            float mx = kz[s * 6];
            for (int u = 1; u < 6; u++) mx = fmaxf(mx, kz[s * 6 + u]);
            float sum = 0.f;
            for (int u = 0; u < 6; u++) { float e = expf(kz[s * 6 + u] - mx); Kr[s][u] = e; sum += e; }
            float invr = 1.f / sum;
            for (int u = 0; u < 6; u++) Kr[s][u] *= invr;
        }
        float pev[6];
        for (int u = 0; u < 6; u++) {
            float a = 0.f;
            for (int s = 0; s < 6; s++) a += spi[s] * Kr[s][u];
            pev[u] = a;
        }
        float mx = ev[0] * 2.f;
        for (int u = 1; u < 6; u++) mx = fmaxf(mx, ev[u] * 2.f);
        float wv[6], sw = 0.f;
        for (int u = 0; u < 6; u++) { wv[u] = expf(ev[u] * 2.f - mx); sw += wv[u]; }
        float invw = 1.f / sw;
        float pn[6], s1 = 0.f;
        for (int u = 0; u < 6; u++) { pn[u] = pev[u] * wv[u] * invw; s1 += pn[u]; }
        float inv1 = 1.f / fmaxf(s1, 1e-8f);
        for (int u = 0; u < 6; u++) pn[u] *= inv1;
        int i1 = 0;
        for (int u = 1; u < 6; u++) if (pn[u] > pn[i1]) i1 = u;
        int i2 = (i1 == 0) ? 1 : 0;
        for (int u = 0; u < 6; u++) if (u != i1 && pn[u] > pn[i2]) i2 = u;
        float inv2 = 1.f / fmaxf(pn[i1] + pn[i2], 1e-8f);
        for (int u = 0; u < 6; u++)
            pi[n * NS + u] = (u == i1 || u == i2) ? pn[u] * inv2 : 0.f;
    }
}

__global__ void attn_k(const float* __restrict__ q, const float* __restrict__ k,
                       const float* __restrict__ v, const float* __restrict__ pi,
                       const float* __restrict__ ln_g, const float* __restrict__ ln_b,
                       float* __restrict__ msg)
{
    __shared__ float sw[4];
    __shared__ float mb[D];
    __shared__ float red[8];
    int n = blockIdx.x, tid = threadIdx.x;
    int t = n % TSEQ;
    int warp = tid >> 5, lane = tid & 31;
    const int offs[4] = {-2, -1, 1, 2};
    {
        int o = offs[warp];
        int tt = t + o;
        float dot = 0.f;
        if (tt >= 0 && tt < TSEQ) {
            const float* qp = q + (long)n * D;
            const float* kp = k + (long)(n + o) * D;
            for (int j = lane; j < D; j += 32) dot += qp[j] * kp[j];
        }
#pragma unroll
        for (int s = 16; s > 0; s >>= 1) dot += __shfl_xor_sync(0xffffffffu, dot, s);
        if (lane == 0)
            sw[warp] = (tt >= 0 && tt < TSEQ) ? dot / 27.712812921102035f : -1e9f;
    }
    __syncthreads();
    float w0 = sw[0], w1 = sw[1], w2 = sw[2], w3 = sw[3];
    float mx = fmaxf(fmaxf(w0, w1), fmaxf(w2, w3));
    float wt[4] = {expf(w0 - mx), expf(w1 - mx), expf(w2 - mx), expf(w3 - mx)};
    float invs = 1.f / (wt[0] + wt[1] + wt[2] + wt[3]);
#pragma unroll
    for (int w = 0; w < 4; w++) wt[w] *= invs;
    float pi3 = pi[n * NS + 3];
    for (int j = tid; j < D; j += 128) {
        float m = 0.f;
#pragma unroll
        for (int w = 0; w < 4; w++) {
            int tt = t + offs[w];
            if (tt >= 0 && tt < TSEQ) m += wt[w] * v[(long)(n + offs[w]) * D + j];
        }
        mb[j] = m * pi3;
    }
    __syncthreads();
    float loc[6], s = 0.f;
#pragma unroll
    for (int r = 0; r < 6; r++) { loc[r] = mb[tid + r * 128]; s += loc[r]; }
    float mean = block_sum(s, red) / D;
    float qv = 0.f;
#pragma unroll
    for (int r = 0; r < 6; r++) { float d = loc[r] - mean; qv += d * d; }
    float var = block_sum(qv, red) / D;
    float inv = rsqrtf(var + 1e-5f);
#pragma unroll
    for (int r = 0; r < 6; r++) {
        int j = tid + r * 128;
        msg[(long)n * D + j] = (loc[r] - mean) * inv * ln_g[3 * D + j] + ln_b[3 * D + j];
    }
}

__global__ void update_k(const float* __restrict__ muhat, float* __restrict__ lam,
                         const float* __restrict__ dlam, const float* __restrict__ mhat,
                         const float* __restrict__ so,
                         const float* __restrict__ ln_g, const float* __restrict__ ln_b,
                         float* __restrict__ mu)
{
    __shared__ float red[8];
    int n = blockIdx.x, tid = threadIdx.x;
    float mval[3], s = 0.f;
#pragma unroll
    for (int r = 0; r < 3; r++) {
        int j = tid + r * 256;
        long idx = (long)n * D + j;
        float l = lam[idx], dl = dlam[idx];
        float mwn = muhat[idx] * ln_g[4 * D + j] + ln_b[4 * D + j];
        float lnw = l + dl;
        float m = (l * mwn + dl * mhat[idx]) / lnw;
        lam[idx] = lnw;
        mval[r] = m;
        s += m;
    }
    float mean = block_sum(s, red) / D;
    float qv = 0.f;
#pragma unroll
    for (int r = 0; r < 3; r++) { float d = mval[r] - mean; qv += d * d; }
    float var = block_sum(qv, red) / D;
    float inv = rsqrtf(var + 1e-5f);
#pragma unroll
    for (int r = 0; r < 3; r++) {
        int j = tid + r * 256;
        long idx = (long)n * D + j;
        mu[idx] = (mval[r] - mean) * inv * ln_g[5 * D + j] + ln_b[5 * D + j] + so[idx] * 0.1f;
    }
}

// ---------------- launcher ----------------
extern "C" void kernel_launch(void* const* d_in, const int* in_sizes, int n_in,
                              void* d_out, int out_size)
{
    const int*   x        = (const int*)d_in[0];
    const float* emb_w    = (const float*)d_in[1];
    const float* pos_w    = (const float*)d_in[2];
    const float* mu_w     = (const float*)d_in[3];
    const float* mu_b     = (const float*)d_in[4];
    const float* lam_w    = (const float*)d_in[5];
    const float* lam_b    = (const float*)d_in[6];
    const float* tr_w1    = (const float*)d_in[7];
    const float* tr_b1    = (const float*)d_in[8];
    const float* tr_w2    = (const float*)d_in[9];
    const float* tr_b2    = (const float*)d_in[10];
    const float* bank_w1  = (const float*)d_in[11];
    const float* bank_b1  = (const float*)d_in[12];
    const float* bank_w2  = (const float*)d_in[13];
    const float* bank_b2  = (const float*)d_in[14];
    const float* ev_w     = (const float*)d_in[15];
    const float* ev_b     = (const float*)d_in[16];
    const float* rt_q     = (const float*)d_in[17];
    const float* rt_k     = (const float*)d_in[18];
    const float* rt_v     = (const float*)d_in[19];
    const float* wr_lam_w = (const float*)d_in[20];
    const float* wr_lam_b = (const float*)d_in[21];
    const float* wr_mu_w  = (const float*)d_in[22];
    const float* wr_mu_b  = (const float*)d_in[23];
    const float* ln_g     = (const float*)d_in[24];
    const float* ln_b     = (const float*)d_in[25];
    float* out = (float*)d_out;

    float* base = nullptr;
    cudaGetSymbolAddress((void**)&base, g_scratch);
    int* cnt = nullptr;
    cudaGetSymbolAddress((void**)&cnt, g_cnt);
    int* list = nullptr;
    cudaGetSymbolAddress((void**)&list, g_list);

    float* h     = base + OFF_H;
    float* mu    = base + OFF_MU;
    float* lam   = base + OFF_LAM;
    float* muhat = base + OFF_MUHAT;
    float* mun   = base + OFF_MUN;
    float* mur   = base + OFF_MUR;
    float* so    = base + OFF_SO;
    float* qb    = base + OFF_Q;
    float* kb    = base + OFF_K;
    float* vb    = base + OFF_V;
    float* msg   = base + OFF_MSG;
    float* dlam  = base + OFF_DLAM;
    float* mhat  = base + OFF_MHAT;
    float* fin   = base + OFF_FIN;
    float* trh   = base + OFF_TRH;
    float* hb    = base + OFF_HB;
    float* pi    = base + OFF_PI;

    const float inv_sqrt_d = 0.03608439182435161f;

    emb_k<<<NTOK, 256>>>(x, emb_w, pos_w, h);
    {
        dim3 g(D / 128, NTOK / 128);
        sgemm_k<EPI_BIAS, false><<<g, 256>>>(h, mu_w, mu_b, mu, NTOK, D, D, nullptr, 0, 1.f);
        sgemm_k<EPI_SP01, false><<<g, 256>>>(h, lam_w, lam_b, lam, NTOK, D, D, nullptr, 0, 1.f);
    }
    pi_init_k<<<(NTOK * NS + 255) / 256, 256>>>(pi);

    for (int step = 0; step < 3; step++) {
        ln012_k<<<NTOK, 256>>>(mu, muhat, mun, mur, ln_g, ln_b);
        {
            dim3 g(1536 / 128, NTOK / 128);
            sgemm_k<EPI_GELU, false><<<g, 256>>>(mu, tr_w1, tr_b1, trh, NTOK, 1536, D, nullptr, 0, 1.f);
        }
        // build per-state token lists from current (pre-update) pi
        reset_cnt_k<<<1, 32>>>(cnt);
        build_lists_k<<<NTOK / 256, 256>>>(pi, cnt, list);
        zero_k<<<(ROW + 255) / 256, 256>>>(so, ROW);
        for (int s = 0; s < NS; s++) {
            dim3 g1(FFN / 128, NTOK / 128);
            bank1_gather_k<<<g1, 256>>>(mun, bank_w1 + (long)s * D * FFN,
                                        bank_b1 + s * FFN, hb,
                                        list + s * NTOK, cnt + s);
            dim3 g2(D / 128, NTOK / 128);
            bank2_scatter_k<<<g2, 256>>>(hb, bank_w2 + (long)s * FFN * D,
                                         bank_b2 + s * D, so,
                                         list + s * NTOK, cnt + s, pi, s);
        }
        ln_gen_k<<<NTOK, 256>>>(so, so, ln_g + 1 * D, ln_b + 1 * D);
        routing_k<<<NTOK, 128>>>(trh, tr_w2, tr_b2, mun, ev_w, ev_b, pi);
        {
            dim3 g(D / 128, NTOK / 128);
            sgemm_k<EPI_NONE, false><<<g, 256>>>(mur, rt_q, nullptr, qb, NTOK, D, D, nullptr, 0, 1.f);
            sgemm_k<EPI_NONE, false><<<g, 256>>>(mur, rt_k, nullptr, kb, NTOK, D, D, nullptr, 0, 1.f);
            sgemm_k<EPI_NONE, false><<<g, 256>>>(mur, rt_v, nullptr, vb, NTOK, D, D, nullptr, 0, 1.f);
        }
        attn_k<<<NTOK, 128>>>(qb, kb, vb, pi, ln_g, ln_b, msg);
        {
            dim3 g(D / 128, NTOK / 128);
            sgemm_k<EPI_GSP, false><<<g, 256>>>(msg, wr_lam_w, wr_lam_b, dlam, NTOK, D, D, pi, 4, 1.f);
            sgemm_k<EPI_BIAS, false><<<g, 256>>>(msg, wr_mu_w, wr_mu_b, mhat, NTOK, D, D, nullptr, 0, 1.f);
        }
        update_k<<<NTOK, 256>>>(muhat, lam, dlam, mhat, so, ln_g, ln_b, mu);
    }

    ln_gen_k<<<NTOK, 256>>>(mu, fin, ln_g + 6 * D, ln_b + 6 * D);
    {
        dim3 g(VOC / 128, NTOK / 128);
        sgemm_k<EPI_SCALE, true><<<g, 256>>>(fin, emb_w, nullptr, out, NTOK, VOC, D,
                                             nullptr, 0, inv_sqrt_d);
    }
}

// round 3
// speedup vs baseline: 1.9734x; 1.4749x over previous
#include <cuda_runtime.h>
#include <math.h>

#define NTOK 2048
#define TSEQ 1024
#define D    768
#define FFN  3072
#define NS   6
#define VOC  32000

// ---------------- scratch (static device memory; no allocs) ----------------
#define ROW (NTOK*D)
#define OFF_H     0
#define OFF_MU    (1*ROW)
#define OFF_LAM   (2*ROW)
#define OFF_MUHAT (3*ROW)
#define OFF_MUN   (4*ROW)
#define OFF_MUR   (5*ROW)
#define OFF_SO    (6*ROW)
#define OFF_Q     (7*ROW)
#define OFF_K     (8*ROW)
#define OFF_V     (9*ROW)
#define OFF_MSG   (10*ROW)
#define OFF_DLAM  (11*ROW)
#define OFF_MHAT  (12*ROW)
#define OFF_FIN   (13*ROW)
#define OFF_TRH   (14*ROW)
#define OFF_HB    (14*ROW + NTOK*1536)
#define OFF_PI    (OFF_HB + NS*NTOK*FFN)
#define SCRATCH_FLOATS (OFF_PI + NTOK*NS)

__device__ float g_scratch[SCRATCH_FLOATS];
__device__ int   g_cnt[NS];            // tokens per state
__device__ int   g_list[NS * NTOK];    // token ids per state (hb row = slot)
__device__ int   g_cnt2[2 * NS];       // per (rank, state)
__device__ int   g_slot2[2 * NS * NTOK];
__device__ int   g_tok2[2 * NS * NTOK];

// ---------------- device helpers ----------------
__device__ __forceinline__ float gelu_f(float x) {
    float x3 = x * x * x;
    return 0.5f * x * (1.f + tanhf(0.7978845608028654f * (x + 0.044715f * x3)));
}
__device__ __forceinline__ float softplus_f(float x) {
    return fmaxf(x, 0.f) + log1pf(expf(-fabsf(x)));
}

__device__ __forceinline__ float block_sum(float v, float* red) {
    int tid = threadIdx.x;
    __syncthreads();
#pragma unroll
    for (int o = 16; o > 0; o >>= 1) v += __shfl_xor_sync(0xffffffffu, v, o);
    if ((tid & 31) == 0) red[tid >> 5] = v;
    __syncthreads();
    if (tid < 32) {
        float t = (tid < (int)(blockDim.x >> 5)) ? red[tid] : 0.f;
#pragma unroll
        for (int o = 4; o > 0; o >>= 1) t += __shfl_xor_sync(0xffffffffu, t, o);
        if (tid == 0) red[0] = t;
    }
    __syncthreads();
    return red[0];
}

// ---------------- GEMM building blocks ----------------
__device__ __forceinline__ void fma_tile(float (&c)[8][8], const float* Asrow,
                                         const float* Bsrow, int ty, int tx)
{
    float4 a0 = *(const float4*)(Asrow + ty * 8);
    float4 a1 = *(const float4*)(Asrow + ty * 8 + 4);
    float4 b0 = *(const float4*)(Bsrow + tx * 8);
    float4 b1 = *(const float4*)(Bsrow + tx * 8 + 4);
    float a[8] = {a0.x, a0.y, a0.z, a0.w, a1.x, a1.y, a1.z, a1.w};
    float b[8] = {b0.x, b0.y, b0.z, b0.w, b1.x, b1.y, b1.z, b1.w};
#pragma unroll
    for (int i = 0; i < 8; i++)
#pragma unroll
        for (int j = 0; j < 8; j++) c[i][j] += a[i] * b[j];
}

// mainloop: As gathered rows (rowIdx in smem) or contiguous (bm0+row)
template <bool GATHER>
__device__ __forceinline__ void gemm_loop(
    const float* __restrict__ A, const float* __restrict__ B,
    int K, int N, int bm0, int bn0, const int* __restrict__ rowIdx,
    float (&c)[8][8], float (*As)[128], float (*Bs)[128])
{
    const int tid = threadIdx.x;
    const int tx = tid & 15, ty = tid >> 4;
    for (int k0 = 0; k0 < K; k0 += 16) {
#pragma unroll
        for (int it = 0; it < 2; it++) {
            int idx = tid + 256 * it;
            int row = idx >> 2, q = idx & 3;
            long gr = GATHER ? (long)rowIdx[row] : (long)(bm0 + row);
            float4 va = *(const float4*)(A + gr * K + k0 + q * 4);
            As[q * 4 + 0][row] = va.x;
            As[q * 4 + 1][row] = va.y;
            As[q * 4 + 2][row] = va.z;
            As[q * 4 + 3][row] = va.w;
        }
#pragma unroll
        for (int it = 0; it < 2; it++) {
            int idx = tid + 256 * it;
            int kr = idx >> 5, n4 = idx & 31;
            float4 vb = *(const float4*)(B + (long)(k0 + kr) * N + bn0 + n4 * 4);
            *(float4*)(&Bs[kr][n4 * 4]) = vb;
        }
        __syncthreads();
#pragma unroll
        for (int kk = 0; kk < 16; kk++) fma_tile(c, As[kk], Bs[kk], ty, tx);
        __syncthreads();
    }
}

// ---------------- dense SGEMM (tr1 gelu, logits TB) ----------------
enum { EPI_NONE = 0, EPI_GELU = 2, EPI_SCALE = 5 };

template <int EPI, bool TB>
__global__ void __launch_bounds__(256, 2) sgemm_k(
    const float* __restrict__ A, const float* __restrict__ B,
    const float* __restrict__ bias, float* __restrict__ C,
    int N, int K, float alpha)
{
    __shared__ float As[16][128];
    __shared__ float Bs[16][128];
    const int tid = threadIdx.x;
    const int bm0 = blockIdx.y * 128;
    const int bn0 = blockIdx.x * 128;
    const int tx = tid & 15, ty = tid >> 4;

    float c[8][8];
#pragma unroll
    for (int i = 0; i < 8; i++)
#pragma unroll
        for (int j = 0; j < 8; j++) c[i][j] = 0.f;

    if (!TB) {
        gemm_loop<false>(A, B, K, N, bm0, bn0, nullptr, c, As, Bs);
    } else {
        for (int k0 = 0; k0 < K; k0 += 16) {
#pragma unroll
            for (int it = 0; it < 2; it++) {
                int idx = tid + 256 * it;
                int row = idx >> 2, q = idx & 3;
                float4 va = *(const float4*)(A + (long)(bm0 + row) * K + k0 + q * 4);
                As[q * 4 + 0][row] = va.x;
                As[q * 4 + 1][row] = va.y;
                As[q * 4 + 2][row] = va.z;
                As[q * 4 + 3][row] = va.w;
            }
#pragma unroll
            for (int it = 0; it < 2; it++) {
                int idx = tid + 256 * it;
                int nc = idx >> 2, q = idx & 3;
                float4 vb = *(const float4*)(B + (long)(bn0 + nc) * K + k0 + q * 4);
                Bs[q * 4 + 0][nc] = vb.x;
                Bs[q * 4 + 1][nc] = vb.y;
                Bs[q * 4 + 2][nc] = vb.z;
                Bs[q * 4 + 3][nc] = vb.w;
            }
            __syncthreads();
#pragma unroll
            for (int kk = 0; kk < 16; kk++) fma_tile(c, As[kk], Bs[kk], ty, tx);
            __syncthreads();
        }
    }

    const int col0 = bn0 + tx * 8;
    float bb[8];
    if (EPI == EPI_GELU) {
#pragma unroll
        for (int j = 0; j < 8; j++) bb[j] = bias[col0 + j];
    }
#pragma unroll
    for (int i = 0; i < 8; i++) {
        int row = bm0 + ty * 8 + i;
        float* cp = C + (long)row * N + col0;
#pragma unroll
        for (int j = 0; j < 8; j++) {
            float v = c[i][j];
            if (EPI == EPI_GELU)       v = gelu_f(v + bb[j]);
            else if (EPI == EPI_SCALE) v = v * alpha;
            cp[j] = v;
        }
    }
}

// ---------------- fused z-dim small GEMMs (N=D, K=D) ----------------
// initpair: z0 -> mu = A@mu_w + b ; z1 -> lam = softplus(A@lam_w + b) + 0.1
__global__ void __launch_bounds__(256, 2) initpair_k(
    const float* __restrict__ A, const float* __restrict__ W0,
    const float* __restrict__ b0, const float* __restrict__ W1,
    const float* __restrict__ b1, float* __restrict__ Cbase)
{
    __shared__ float As[16][128];
    __shared__ float Bs[16][128];
    const int z = blockIdx.z;
    const float* B = z ? W1 : W0;
    const float* bias = z ? b1 : b0;
    float* C = Cbase + (long)z * ROW;
    const int bm0 = blockIdx.y * 128, bn0 = blockIdx.x * 128;
    const int tid = threadIdx.x, tx = tid & 15, ty = tid >> 4;
    float c[8][8];
#pragma unroll
    for (int i = 0; i < 8; i++)
#pragma unroll
        for (int j = 0; j < 8; j++) c[i][j] = 0.f;
    gemm_loop<false>(A, B, D, D, bm0, bn0, nullptr, c, As, Bs);
    const int col0 = bn0 + tx * 8;
    float bb[8];
#pragma unroll
    for (int j = 0; j < 8; j++) bb[j] = bias[col0 + j];
#pragma unroll
    for (int i = 0; i < 8; i++) {
        float* cp = C + (long)(bm0 + ty * 8 + i) * D + col0;
#pragma unroll
        for (int j = 0; j < 8; j++) {
            float v = c[i][j] + bb[j];
            cp[j] = z ? (softplus_f(v) + 0.1f) : v;
        }
    }
}

// qkv: z in {0,1,2} -> {q,k,v} = mur @ {rt_q,rt_k,rt_v}
__global__ void __launch_bounds__(256, 2) qkv_k(
    const float* __restrict__ A, const float* __restrict__ Wq,
    const float* __restrict__ Wk, const float* __restrict__ Wv,
    float* __restrict__ Cbase)
{
    __shared__ float As[16][128];
    __shared__ float Bs[16][128];
    const int z = blockIdx.z;
    const float* B = (z == 0) ? Wq : (z == 1) ? Wk : Wv;
    float* C = Cbase + (long)z * ROW;
    const int bm0 = blockIdx.y * 128, bn0 = blockIdx.x * 128;
    const int tid = threadIdx.x, tx = tid & 15, ty = tid >> 4;
    float c[8][8];
#pragma unroll
    for (int i = 0; i < 8; i++)
#pragma unroll
        for (int j = 0; j < 8; j++) c[i][j] = 0.f;
    gemm_loop<false>(A, B, D, D, bm0, bn0, nullptr, c, As, Bs);
    const int col0 = bn0 + tx * 8;
#pragma unroll
    for (int i = 0; i < 8; i++) {
        float* cp = C + (long)(bm0 + ty * 8 + i) * D + col0;
#pragma unroll
        for (int j = 0; j < 8; j++) cp[j] = c[i][j];
    }
}

// wrpair: z0 -> dlam = pi4*softplus(msg@wr_lam + b) ; z1 -> mhat = msg@wr_mu + b
__global__ void __launch_bounds__(256, 2) wrpair_k(
    const float* __restrict__ A, const float* __restrict__ W0,
    const float* __restrict__ b0, const float* __restrict__ W1,
    const float* __restrict__ b1, const float* __restrict__ pi,
    float* __restrict__ Cbase)
{
    __shared__ float As[16][128];
    __shared__ float Bs[16][128];
    const int z = blockIdx.z;
    const float* B = z ? W1 : W0;
    const float* bias = z ? b1 : b0;
    float* C = Cbase + (long)z * ROW;
    const int bm0 = blockIdx.y * 128, bn0 = blockIdx.x * 128;
    const int tid = threadIdx.x, tx = tid & 15, ty = tid >> 4;
    float c[8][8];
#pragma unroll
    for (int i = 0; i < 8; i++)
#pragma unroll
        for (int j = 0; j < 8; j++) c[i][j] = 0.f;
    gemm_loop<false>(A, B, D, D, bm0, bn0, nullptr, c, As, Bs);
    const int col0 = bn0 + tx * 8;
    float bb[8];
#pragma unroll
    for (int j = 0; j < 8; j++) bb[j] = bias[col0 + j];
#pragma unroll
    for (int i = 0; i < 8; i++) {
        int row = bm0 + ty * 8 + i;
        float rs = pi[row * NS + 4];
        float* cp = C + (long)row * D + col0;
#pragma unroll
        for (int j = 0; j < 8; j++) {
            float v = c[i][j] + bb[j];
            cp[j] = z ? v : rs * softplus_f(v);
        }
    }
}

// ---------------- fused-state bank GEMMs ----------------
// bank1: all states in one launch. hb[s][slot] = gelu(mun[tok]@W1_s + b1_s)
__global__ void __launch_bounds__(256, 2) bank1_all_k(
    const float* __restrict__ A, const float* __restrict__ W1all,
    const float* __restrict__ b1all, float* __restrict__ hb,
    const int* __restrict__ list, const int* __restrict__ cnt)
{
    const int s = blockIdx.z;
    const int cn = cnt[s];
    const int bm0 = blockIdx.y * 128;
    if (bm0 >= cn) return;
    __shared__ float As[16][128];
    __shared__ float Bs[16][128];
    __shared__ int rowTok[128];
    const int tid = threadIdx.x;
    const int bn0 = blockIdx.x * 128;
    const int tx = tid & 15, ty = tid >> 4;
    if (tid < 128) rowTok[tid] = list[s * NTOK + min(bm0 + tid, cn - 1)];
    __syncthreads();

    const float* B = W1all + (long)s * D * FFN;
    const float* bias = b1all + s * FFN;
    float* C = hb + (long)s * NTOK * FFN;

    float c[8][8];
#pragma unroll
    for (int i = 0; i < 8; i++)
#pragma unroll
        for (int j = 0; j < 8; j++) c[i][j] = 0.f;
    gemm_loop<true>(A, B, D, FFN, 0, bn0, rowTok, c, As, Bs);

    const int col0 = bn0 + tx * 8;
    float bb[8];
#pragma unroll
    for (int j = 0; j < 8; j++) bb[j] = bias[col0 + j];
#pragma unroll
    for (int i = 0; i < 8; i++) {
        int slot = bm0 + ty * 8 + i;
        if (slot >= cn) continue;
        float* cp = C + (long)slot * FFN + col0;
#pragma unroll
        for (int j = 0; j < 8; j++) cp[j] = gelu_f(c[i][j] + bb[j]);
    }
}

// bank2: rank pass. RANK=0 assigns so rows, RANK=1 accumulates. Tokens within a
// rank are disjoint across states -> no races, deterministic.
template <int RANK>
__global__ void __launch_bounds__(256, 2) bank2_all_k(
    const float* __restrict__ hb, const float* __restrict__ W2all,
    const float* __restrict__ b2all, float* __restrict__ so,
    const int* __restrict__ cnt2, const int* __restrict__ slot2,
    const int* __restrict__ tok2, const float* __restrict__ pi)
{
    const int s = blockIdx.z;
    const int cn = cnt2[RANK * NS + s];
    const int bm0 = blockIdx.y * 128;
    if (bm0 >= cn) return;
    __shared__ float As[16][128];
    __shared__ float Bs[16][128];
    __shared__ int rowSlot[128];
    const int tid = threadIdx.x;
    const int bn0 = blockIdx.x * 128;
    const int tx = tid & 15, ty = tid >> 4;
    const int lbase = (RANK * NS + s) * NTOK;
    if (tid < 128) rowSlot[tid] = slot2[lbase + min(bm0 + tid, cn - 1)];
    __syncthreads();

    const float* A = hb + (long)s * NTOK * FFN;
    const float* B = W2all + (long)s * FFN * D;
    const float* bias = b2all + s * D;

    float c[8][8];
#pragma unroll
    for (int i = 0; i < 8; i++)
#pragma unroll
        for (int j = 0; j < 8; j++) c[i][j] = 0.f;
    gemm_loop<true>(A, B, FFN, D, 0, bn0, rowSlot, c, As, Bs);

    const int col0 = bn0 + tx * 8;
    float bb[8];
#pragma unroll
    for (int j = 0; j < 8; j++) bb[j] = bias[col0 + j];
#pragma unroll
    for (int i = 0; i < 8; i++) {
        int idx = bm0 + ty * 8 + i;
        if (idx >= cn) continue;
        int tok = tok2[lbase + idx];
        float rs = pi[tok * NS + s];
        float* cp = so + (long)tok * D + col0;
#pragma unroll
        for (int j = 0; j < 8; j++) {
            float v = rs * (c[i][j] + bb[j]);
            if (RANK == 0) cp[j] = v;
            else           cp[j] += v;
        }
    }
}

// ---------------- small kernels ----------------
__global__ void emb_k(const int* __restrict__ x, const float* __restrict__ emb,
                      const float* __restrict__ pos, float* __restrict__ h)
{
    int n = blockIdx.x;
    int vx = x[n];
    int t = n % TSEQ;
    const float* e = emb + (long)vx * D;
    const float* p = pos + (long)t * D;
    for (int j = threadIdx.x; j < D; j += blockDim.x)
        h[(long)n * D + j] = e[j] + p[j];
}

__global__ void pi_init_k(float* __restrict__ pi)
{
    int i = blockIdx.x * blockDim.x + threadIdx.x;
    if (i < NTOK * NS) pi[i] = ((i % NS) == 2) ? 1.f : 0.f;
}

__global__ void reset_cnt_k(int* cnt, int* cnt2)
{
    if (threadIdx.x < NS) cnt[threadIdx.x] = 0;
    if (threadIdx.x < 2 * NS) cnt2[threadIdx.x] = 0;
}

__global__ void build_lists_k(const float* __restrict__ pi,
                              int* __restrict__ cnt, int* __restrict__ list,
                              int* __restrict__ cnt2, int* __restrict__ slot2,
                              int* __restrict__ tok2)
{
    int t = blockIdx.x * blockDim.x + threadIdx.x;
    if (t >= NTOK) return;
    int r = 0;
#pragma unroll
    for (int s = 0; s < NS; s++) {
        if (pi[t * NS + s] != 0.f) {
            int p = atomicAdd(&cnt[s], 1);
            list[s * NTOK + p] = t;
            int rr = min(r, 1);
            int q = atomicAdd(&cnt2[rr * NS + s], 1);
            slot2[(rr * NS + s) * NTOK + q] = p;
            tok2[(rr * NS + s) * NTOK + q] = t;
            r++;
        }
    }
}

__global__ void ln012_k(const float* __restrict__ mu, float* __restrict__ muhat,
                        float* __restrict__ mun, float* __restrict__ mur,
                        const float* __restrict__ ln_g, const float* __restrict__ ln_b)
{
    __shared__ float red[8];
    int n = blockIdx.x, tid = threadIdx.x;
    const float* row = mu + (long)n * D;
    float v[3], s = 0.f;
#pragma unroll
    for (int r = 0; r < 3; r++) { v[r] = row[tid + r * 256]; s += v[r]; }
    float mean = block_sum(s, red) / D;
    float qv = 0.f;
#pragma unroll
    for (int r = 0; r < 3; r++) { float d = v[r] - mean; qv += d * d; }
    float var = block_sum(qv, red) / D;
    float inv = rsqrtf(var + 1e-5f);
#pragma unroll
    for (int r = 0; r < 3; r++) {
        int j = tid + r * 256;
        float nh = (v[r] - mean) * inv;
        long idx = (long)n * D + j;
        muhat[idx] = nh;
        mun[idx] = nh * ln_g[j] + ln_b[j];
        mur[idx] = nh * ln_g[2 * D + j] + ln_b[2 * D + j];
    }
}

__global__ void ln_gen_k(const float* __restrict__ in, float* __restrict__ out,
                         const float* __restrict__ g, const float* __restrict__ b)
{
    __shared__ float red[8];
    int n = blockIdx.x, tid = threadIdx.x;
    const float* row = in + (long)n * D;
    float v[3], s = 0.f;
#pragma unroll
    for (int r = 0; r < 3; r++) { v[r] = row[tid + r * 256]; s += v[r]; }
    float mean = block_sum(s, red) / D;
    float qv = 0.f;
#pragma unroll
    for (int r = 0; r < 3; r++) { float d = v[r] - mean; qv += d * d; }
    float var = block_sum(qv, red) / D;
    float inv = rsqrtf(var + 1e-5f);
#pragma unroll
    for (int r = 0; r < 3; r++) {
        int j = tid + r * 256;
        out[(long)n * D + j] = (v[r] - mean) * inv * g[j] + b[j];
    }
}

__global__ void routing_k(const float* __restrict__ trh, const float* __restrict__ w2,
                          const float* __restrict__ b2, const float* __restrict__ mun,
                          const float* __restrict__ evw, const float* __restrict__ evb,
                          float* __restrict__ pi)
{
    __shared__ float sh[1536];
    __shared__ float sm[D];
    __shared__ float kz[36];
    __shared__ float ev[6];
    __shared__ float spi[6];
    int n = blockIdx.x, tid = threadIdx.x;
    for (int i = tid; i < 1536; i += 128) sh[i] = trh[(long)n * 1536 + i];
    for (int i = tid; i < D; i += 128)    sm[i] = mun[(long)n * D + i];
    if (tid < NS) spi[tid] = pi[n * NS + tid];
    __syncthreads();
    if (tid < 36) {
        float acc = b2[tid];
        for (int k = 0; k < 1536; k++) acc += sh[k] * w2[k * 36 + tid];
        kz[tid] = acc;
    } else if (tid < 42) {
        int j = tid - 36;
        float acc = evb[j];
        for (int k = 0; k < D; k++) acc += sm[k] * evw[k * NS + j];
        ev[j] = acc;
    }
    __syncthreads();
    if (tid == 0) {
        float Kr[6][6];
        for (int s = 0; s < 6; s++) {
            float mx = kz[s * 6];
            for (int u = 1; u < 6; u++) mx = fmaxf(mx, kz[s * 6 + u]);
            float sum = 0.f;
            for (int u = 0; u < 6; u++) { float e = expf(kz[s * 6 + u] - mx); Kr[s][u] = e; sum += e; }
            float invr = 1.f / sum;
            for (int u = 0; u < 6; u++) Kr[s][u] *= invr;
        }
        float pev[6];
        for (int u = 0; u < 6; u++) {
            float a = 0.f;
            for (int s = 0; s < 6; s++) a += spi[s] * Kr[s][u];
            pev[u] = a;
        }
        float mx = ev[0] * 2.f;
        for (int u = 1; u < 6; u++) mx = fmaxf(mx, ev[u] * 2.f);
        float wv[6], sw = 0.f;
        for (int u = 0; u < 6; u++) { wv[u] = expf(ev[u] * 2.f - mx); sw += wv[u]; }
        float invw = 1.f / sw;
        float pn[6], s1 = 0.f;
        for (int u = 0; u < 6; u++) { pn[u] = pev[u] * wv[u] * invw; s1 += pn[u]; }
        float inv1 = 1.f / fmaxf(s1, 1e-8f);
        for (int u = 0; u < 6; u++) pn[u] *= inv1;
        int i1 = 0;
        for (int u = 1; u < 6; u++) if (pn[u] > pn[i1]) i1 = u;
        int i2 = (i1 == 0) ? 1 : 0;
        for (int u = 0; u < 6; u++) if (u != i1 && pn[u] > pn[i2]) i2 = u;
        float inv2 = 1.f / fmaxf(pn[i1] + pn[i2], 1e-8f);
        for (int u = 0; u < 6; u++)
            pi[n * NS + u] = (u == i1 || u == i2) ? pn[u] * inv2 : 0.f;
    }
}

__global__ void attn_k(const float* __restrict__ q, const float* __restrict__ k,
                       const float* __restrict__ v, const float* __restrict__ pi,
                       const float* __restrict__ ln_g, const float* __restrict__ ln_b,
                       float* __restrict__ msg)
{
    __shared__ float sw[4];
    __shared__ float mb[D];
    __shared__ float red[8];
    int n = blockIdx.x, tid = threadIdx.x;
    int t = n % TSEQ;
    int warp = tid >> 5, lane = tid & 31;
    const int offs[4] = {-2, -1, 1, 2};
    {
        int o = offs[warp];
        int tt = t + o;
        float dot = 0.f;
        if (tt >= 0 && tt < TSEQ) {
            const float* qp = q + (long)n * D;
            const float* kp = k + (long)(n + o) * D;
            for (int j = lane; j < D; j += 32) dot += qp[j] * kp[j];
        }
#pragma unroll
        for (int s = 16; s > 0; s >>= 1) dot += __shfl_xor_sync(0xffffffffu, dot, s);
        if (lane == 0)
            sw[warp] = (tt >= 0 && tt < TSEQ) ? dot / 27.712812921102035f : -1e9f;
    }
    __syncthreads();
    float w0 = sw[0], w1 = sw[1], w2 = sw[2], w3 = sw[3];
    float mx = fmaxf(fmaxf(w0, w1), fmaxf(w2, w3));
    float wt[4] = {expf(w0 - mx), expf(w1 - mx), expf(w2 - mx), expf(w3 - mx)};
    float invs = 1.f / (wt[0] + wt[1] + wt[2] + wt[3]);
#pragma unroll
    for (int w = 0; w < 4; w++) wt[w] *= invs;
    float pi3 = pi[n * NS + 3];
    for (int j = tid; j < D; j += 128) {
        float m = 0.f;
#pragma unroll
        for (int w = 0; w < 4; w++) {
            int tt = t + offs[w];
            if (tt >= 0 && tt < TSEQ) m += wt[w] * v[(long)(n + offs[w]) * D + j];
        }
        mb[j] = m * pi3;
    }
    __syncthreads();
    float loc[6], s = 0.f;
#pragma unroll
    for (int r = 0; r < 6; r++) { loc[r] = mb[tid + r * 128]; s += loc[r]; }
    float mean = block_sum(s, red) / D;
    float qv = 0.f;
#pragma unroll
    for (int r = 0; r < 6; r++) { float d = loc[r] - mean; qv += d * d; }
    float var = block_sum(qv, red) / D;
    float inv = rsqrtf(var + 1e-5f);
#pragma unroll
    for (int r = 0; r < 6; r++) {
        int j = tid + r * 128;
        msg[(long)n * D + j] = (loc[r] - mean) * inv * ln_g[3 * D + j] + ln_b[3 * D + j];
    }
}

__global__ void update_k(const float* __restrict__ muhat, float* __restrict__ lam,
                         const float* __restrict__ dlam, const float* __restrict__ mhat,
                         const float* __restrict__ so,
                         const float* __restrict__ ln_g, const float* __restrict__ ln_b,
                         float* __restrict__ mu)
{
    __shared__ float red[8];
    int n = blockIdx.x, tid = threadIdx.x;
    float mval[3], s = 0.f;
#pragma unroll
    for (int r = 0; r < 3; r++) {
        int j = tid + r * 256;
        long idx = (long)n * D + j;
        float l = lam[idx], dl = dlam[idx];
        float mwn = muhat[idx] * ln_g[4 * D + j] + ln_b[4 * D + j];
        float lnw = l + dl;
        float m = (l * mwn + dl * mhat[idx]) / lnw;
        lam[idx] = lnw;
        mval[r] = m;
        s += m;
    }
    float mean = block_sum(s, red) / D;
    float qv = 0.f;
#pragma unroll
    for (int r = 0; r < 3; r++) { float d = mval[r] - mean; qv += d * d; }
    float var = block_sum(qv, red) / D;
    float inv = rsqrtf(var + 1e-5f);
#pragma unroll
    for (int r = 0; r < 3; r++) {
        int j = tid + r * 256;
        long idx = (long)n * D + j;
        mu[idx] = (mval[r] - mean) * inv * ln_g[5 * D + j] + ln_b[5 * D + j] + so[idx] * 0.1f;
    }
}

// ---------------- launcher ----------------
extern "C" void kernel_launch(void* const* d_in, const int* in_sizes, int n_in,
                              void* d_out, int out_size)
{
    const int*   x        = (const int*)d_in[0];
    const float* emb_w    = (const float*)d_in[1];
    const float* pos_w    = (const float*)d_in[2];
    const float* mu_w     = (const float*)d_in[3];
    const float* mu_b     = (const float*)d_in[4];
    const float* lam_w    = (const float*)d_in[5];
    const float* lam_b    = (const float*)d_in[6];
    const float* tr_w1    = (const float*)d_in[7];
    const float* tr_b1    = (const float*)d_in[8];
    const float* tr_w2    = (const float*)d_in[9];
    const float* tr_b2    = (const float*)d_in[10];
    const float* bank_w1  = (const float*)d_in[11];
    const float* bank_b1  = (const float*)d_in[12];
    const float* bank_w2  = (const float*)d_in[13];
    const float* bank_b2  = (const float*)d_in[14];
    const float* ev_w     = (const float*)d_in[15];
    const float* ev_b     = (const float*)d_in[16];
    const float* rt_q     = (const float*)d_in[17];
    const float* rt_k     = (const float*)d_in[18];
    const float* rt_v     = (const float*)d_in[19];
    const float* wr_lam_w = (const float*)d_in[20];
    const float* wr_lam_b = (const float*)d_in[21];
    const float* wr_mu_w  = (const float*)d_in[22];
    const float* wr_mu_b  = (const float*)d_in[23];
    const float* ln_g     = (const float*)d_in[24];
    const float* ln_b     = (const float*)d_in[25];
    float* out = (float*)d_out;

    float* base = nullptr;
    cudaGetSymbolAddress((void**)&base, g_scratch);
    int *cnt, *list, *cnt2, *slot2, *tok2;
    cudaGetSymbolAddress((void**)&cnt, g_cnt);
    cudaGetSymbolAddress((void**)&list, g_list);
    cudaGetSymbolAddress((void**)&cnt2, g_cnt2);
    cudaGetSymbolAddress((void**)&slot2, g_slot2);
    cudaGetSymbolAddress((void**)&tok2, g_tok2);

    float* h     = base + OFF_H;
    float* mu    = base + OFF_MU;
    float* muhat = base + OFF_MUHAT;
    float* mun   = base + OFF_MUN;
    float* mur   = base + OFF_MUR;
    float* so    = base + OFF_SO;
    float* qb    = base + OFF_Q;
    float* lam   = base + OFF_LAM;
    float* msg   = base + OFF_MSG;
    float* dlam  = base + OFF_DLAM;
    float* mhat  = base + OFF_MHAT;
    float* fin   = base + OFF_FIN;
    float* trh   = base + OFF_TRH;
    float* hb    = base + OFF_HB;
    float* pi    = base + OFF_PI;

    const float inv_sqrt_d = 0.03608439182435161f;

    emb_k<<<NTOK, 256>>>(x, emb_w, pos_w, h);
    {
        dim3 g(D / 128, NTOK / 128, 2);
        initpair_k<<<g, 256>>>(h, mu_w, mu_b, lam_w, lam_b, mu); // mu at z=0, lam at z=1 (adjacent)
    }
    pi_init_k<<<(NTOK * NS + 255) / 256, 256>>>(pi);

    for (int step = 0; step < 3; step++) {
        ln012_k<<<NTOK, 256>>>(mu, muhat, mun, mur, ln_g, ln_b);
        {
            dim3 g(1536 / 128, NTOK / 128);
            sgemm_k<EPI_GELU, false><<<g, 256>>>(mu, tr_w1, tr_b1, trh, 1536, D, 1.f);
        }
        reset_cnt_k<<<1, 32>>>(cnt, cnt2);
        build_lists_k<<<NTOK / 256, 256>>>(pi, cnt, list, cnt2, slot2, tok2);
        {
            dim3 g1(FFN / 128, NTOK / 128, NS);
            bank1_all_k<<<g1, 256>>>(mun, bank_w1, bank_b1, hb, list, cnt);
            dim3 g2(D / 128, NTOK / 128, NS);
            bank2_all_k<0><<<g2, 256>>>(hb, bank_w2, bank_b2, so, cnt2, slot2, tok2, pi);
            bank2_all_k<1><<<g2, 256>>>(hb, bank_w2, bank_b2, so, cnt2, slot2, tok2, pi);
        }
        ln_gen_k<<<NTOK, 256>>>(so, so, ln_g + 1 * D, ln_b + 1 * D);
        routing_k<<<NTOK, 128>>>(trh, tr_w2, tr_b2, mun, ev_w, ev_b, pi);
        {
            dim3 g(D / 128, NTOK / 128, 3);
            qkv_k<<<g, 256>>>(mur, rt_q, rt_k, rt_v, qb); // q,k,v adjacent
        }
        attn_k<<<NTOK, 128>>>(qb, qb + ROW, qb + 2 * ROW, pi, ln_g, ln_b, msg);
        {
            dim3 g(D / 128, NTOK / 128, 2);
            wrpair_k<<<g, 256>>>(msg, wr_lam_w, wr_lam_b, wr_mu_w, wr_mu_b, pi, dlam); // dlam,mhat adjacent
        }
        update_k<<<NTOK, 256>>>(muhat, lam, dlam, mhat, so, ln_g, ln_b, mu);
    }

    ln_gen_k<<<NTOK, 256>>>(mu, fin, ln_g + 6 * D, ln_b + 6 * D);
    {
        dim3 g(VOC / 128, NTOK / 128);
        sgemm_k<EPI_SCALE, true><<<g, 256>>>(fin, emb_w, nullptr, out, VOC, D, inv_sqrt_d);
    }
}

// round 4
// speedup vs baseline: 2.3231x; 1.1773x over previous
#include <cuda_runtime.h>
#include <math.h>
#include <stdint.h>

#define NTOK 2048
#define TSEQ 1024
#define D    768
#define FFN  3072
#define NS   6
#define VOC  32000

// ---------------- scratch ----------------
#define ROW (NTOK*D)
#define OFF_H     0
#define OFF_MU    (1*ROW)
#define OFF_LAM   (2*ROW)
#define OFF_MUHAT (3*ROW)
#define OFF_MUN   (4*ROW)
#define OFF_MUR   (5*ROW)
#define OFF_SO    (6*ROW)
#define OFF_Q     (7*ROW)
#define OFF_K     (8*ROW)
#define OFF_V     (9*ROW)
#define OFF_MSG   (10*ROW)
#define OFF_DLAM  (11*ROW)
#define OFF_MHAT  (12*ROW)
#define OFF_FIN   (13*ROW)
#define OFF_TRH   (14*ROW)
#define OFF_HB    (14*ROW + NTOK*1536)
#define OFF_PI    (OFF_HB + NS*NTOK*FFN)
#define SCRATCH_FLOATS (OFF_PI + NTOK*NS)

__device__ float g_scratch[SCRATCH_FLOATS];
__device__ int   g_cnt[NS];
__device__ int   g_list[NS * NTOK];
__device__ int   g_cnt2[2 * NS];
__device__ int   g_slot2[2 * NS * NTOK];
__device__ int   g_tok2[2 * NS * NTOK];

// ---------------- helpers ----------------
__device__ __forceinline__ float gelu_f(float x) {
    float x3 = x * x * x;
    return 0.5f * x * (1.f + tanhf(0.7978845608028654f * (x + 0.044715f * x3)));
}
__device__ __forceinline__ float softplus_f(float x) {
    return fmaxf(x, 0.f) + log1pf(expf(-fabsf(x)));
}
__device__ __forceinline__ float block_sum(float v, float* red) {
    int tid = threadIdx.x;
    __syncthreads();
#pragma unroll
    for (int o = 16; o > 0; o >>= 1) v += __shfl_xor_sync(0xffffffffu, v, o);
    if ((tid & 31) == 0) red[tid >> 5] = v;
    __syncthreads();
    if (tid < 32) {
        float t = (tid < (int)(blockDim.x >> 5)) ? red[tid] : 0.f;
#pragma unroll
        for (int o = 4; o > 0; o >>= 1) t += __shfl_xor_sync(0xffffffffu, t, o);
        if (tid == 0) red[0] = t;
    }
    __syncthreads();
    return red[0];
}

// ---------------- tf32 mma core ----------------
#define AS_STRIDE 20
#define BS_STRIDE 136

__device__ __forceinline__ void cvt_split(float x, float& hi, float& lo) {
    uint32_t hb; asm("cvt.rna.tf32.f32 %0, %1;" : "=r"(hb) : "f"(x));
    hi = __uint_as_float(hb);
    float lf = x - hi;
    uint32_t lb; asm("cvt.rna.tf32.f32 %0, %1;" : "=r"(lb) : "f"(lf));
    lo = __uint_as_float(lb);
}

__device__ __forceinline__ void mma8(float* c, const uint32_t* a, uint32_t b0, uint32_t b1) {
    asm volatile(
        "mma.sync.aligned.m16n8k8.row.col.f32.tf32.tf32.f32 "
        "{%0,%1,%2,%3},{%4,%5,%6,%7},{%8,%9},{%0,%1,%2,%3};"
        : "+f"(c[0]), "+f"(c[1]), "+f"(c[2]), "+f"(c[3])
        : "r"(a[0]), "r"(a[1]), "r"(a[2]), "r"(a[3]), "r"(b0), "r"(b1));
}

// mainloop: block 128x128, 8 warps (4m x 2n), warp tile 32x64, BK=16
template <bool TB, bool GATHER>
__device__ __forceinline__ void tf32_loop(
    const float* __restrict__ A, const float* __restrict__ B,
    int K, int N, int bm0, int bn0, const int* __restrict__ rowTok,
    float (*Ahi)[AS_STRIDE], float (*Alo)[AS_STRIDE],
    float (*Bhi)[BS_STRIDE], float (*Blo)[BS_STRIDE],
    float c[2][8][4])
{
    const int tid = threadIdx.x;
    const int lane = tid & 31, warp = tid >> 5;
    const int wm0 = (warp >> 1) * 32, wn0 = (warp & 1) * 64;
    const int g = lane >> 2, tig = lane & 3;

    for (int k0 = 0; k0 < K; k0 += 16) {
#pragma unroll
        for (int it = 0; it < 2; it++) {
            int idx = tid + 256 * it;
            int row = idx >> 2, q = idx & 3;
            long gr = GATHER ? (long)rowTok[row] : (long)(bm0 + row);
            float4 v = *(const float4*)(A + gr * K + k0 + q * 4);
            float xs[4] = {v.x, v.y, v.z, v.w};
#pragma unroll
            for (int j = 0; j < 4; j++) {
                float hf, lf;
                cvt_split(xs[j], hf, lf);
                Ahi[row][q * 4 + j] = hf;
                Alo[row][q * 4 + j] = lf;
            }
        }
        if (!TB) {
#pragma unroll
            for (int it = 0; it < 2; it++) {
                int idx = tid + 256 * it;
                int kr = idx >> 5, n4 = idx & 31;
                float4 v = *(const float4*)(B + (long)(k0 + kr) * N + bn0 + n4 * 4);
                float xs[4] = {v.x, v.y, v.z, v.w};
#pragma unroll
                for (int j = 0; j < 4; j++) {
                    float hf, lf;
                    cvt_split(xs[j], hf, lf);
                    Bhi[kr][n4 * 4 + j] = hf;
                    Blo[kr][n4 * 4 + j] = lf;
                }
            }
        } else {
#pragma unroll
            for (int it = 0; it < 2; it++) {
                int idx = tid + 256 * it;
                int nc = idx >> 2, q = idx & 3;
                float4 v = *(const float4*)(B + (long)(bn0 + nc) * K + k0 + q * 4);
                float xs[4] = {v.x, v.y, v.z, v.w};
#pragma unroll
                for (int j = 0; j < 4; j++) {
                    float hf, lf;
                    cvt_split(xs[j], hf, lf);
                    Bhi[q * 4 + j][nc] = hf;
                    Blo[q * 4 + j][nc] = lf;
                }
            }
        }
        __syncthreads();
#pragma unroll
        for (int ks = 0; ks < 16; ks += 8) {
            uint32_t ah[2][4], al[2][4];
#pragma unroll
            for (int mt = 0; mt < 2; mt++) {
                int rb = wm0 + mt * 16 + g;
                ah[mt][0] = __float_as_uint(Ahi[rb][ks + tig]);
                ah[mt][1] = __float_as_uint(Ahi[rb + 8][ks + tig]);
                ah[mt][2] = __float_as_uint(Ahi[rb][ks + tig + 4]);
                ah[mt][3] = __float_as_uint(Ahi[rb + 8][ks + tig + 4]);
                al[mt][0] = __float_as_uint(Alo[rb][ks + tig]);
                al[mt][1] = __float_as_uint(Alo[rb + 8][ks + tig]);
                al[mt][2] = __float_as_uint(Alo[rb][ks + tig + 4]);
                al[mt][3] = __float_as_uint(Alo[rb + 8][ks + tig + 4]);
            }
#pragma unroll
            for (int nt = 0; nt < 8; nt++) {
                int cb = wn0 + nt * 8 + g;
                uint32_t bh0 = __float_as_uint(Bhi[ks + tig][cb]);
                uint32_t bh1 = __float_as_uint(Bhi[ks + tig + 4][cb]);
                uint32_t bl0 = __float_as_uint(Blo[ks + tig][cb]);
                uint32_t bl1 = __float_as_uint(Blo[ks + tig + 4][cb]);
#pragma unroll
                for (int mt = 0; mt < 2; mt++) {
                    mma8(c[mt][nt], ah[mt], bh0, bh1);
                    mma8(c[mt][nt], ah[mt], bl0, bl1);
                    mma8(c[mt][nt], al[mt], bh0, bh1);
                }
            }
        }
        __syncthreads();
    }
}

// ---------------- epilogues ----------------
enum { EPI_NONE = 0, EPI_BIAS = 1, EPI_GELU = 2, EPI_GSP = 3, EPI_SCALE = 4, EPI_SP01 = 5 };

template <int EPI>
__device__ __forceinline__ float epi_apply(float v, float b, float rs, float alpha) {
    if (EPI == EPI_BIAS)  return v + b;
    if (EPI == EPI_GELU)  return gelu_f(v + b);
    if (EPI == EPI_GSP)   return rs * softplus_f(v + b);
    if (EPI == EPI_SCALE) return v * alpha;
    if (EPI == EPI_SP01)  return softplus_f(v + b) + 0.1f;
    return v;
}

template <int EPI>
__device__ __forceinline__ void epi_store_dense(
    float c[2][8][4], float* __restrict__ C, const float* __restrict__ bias,
    int N, int bm0, int bn0, const float* __restrict__ pi, float alpha)
{
    const int tid = threadIdx.x, lane = tid & 31, warp = tid >> 5;
    const int wm0 = (warp >> 1) * 32, wn0 = (warp & 1) * 64;
    const int g = lane >> 2, tig = lane & 3;
    const int colbase = bn0 + wn0;
#pragma unroll
    for (int mt = 0; mt < 2; mt++) {
#pragma unroll
        for (int half = 0; half < 2; half++) {
            int row = bm0 + wm0 + mt * 16 + g + half * 8;
            float rs = (EPI == EPI_GSP) ? pi[row * NS + 4] : 0.f;
            float* cp = C + (long)row * N + colbase;
#pragma unroll
            for (int nt = 0; nt < 8; nt++) {
                int col = nt * 8 + tig * 2;
                float b0 = 0.f, b1 = 0.f;
                if (EPI == EPI_BIAS || EPI == EPI_GELU || EPI == EPI_GSP || EPI == EPI_SP01) {
                    b0 = bias[colbase + col];
                    b1 = bias[colbase + col + 1];
                }
                float v0 = epi_apply<EPI>(c[mt][nt][half * 2], b0, rs, alpha);
                float v1 = epi_apply<EPI>(c[mt][nt][half * 2 + 1], b1, rs, alpha);
                *(float2*)(cp + col) = make_float2(v0, v1);
            }
        }
    }
}

// ---------------- GEMM kernels ----------------
template <int EPI, bool TB>
__global__ void __launch_bounds__(256, 2) tgemm_k(
    const float* __restrict__ A, const float* __restrict__ B,
    const float* __restrict__ bias, float* __restrict__ C,
    int N, int K, float alpha, const float* __restrict__ pi)
{
    __shared__ float Ahi[128][AS_STRIDE], Alo[128][AS_STRIDE];
    __shared__ float Bhi[16][BS_STRIDE], Blo[16][BS_STRIDE];
    const int bm0 = blockIdx.y * 128, bn0 = blockIdx.x * 128;
    float c[2][8][4];
#pragma unroll
    for (int a = 0; a < 2; a++)
#pragma unroll
        for (int b = 0; b < 8; b++)
#pragma unroll
            for (int r = 0; r < 4; r++) c[a][b][r] = 0.f;
    tf32_loop<TB, false>(A, B, K, N, bm0, bn0, nullptr, Ahi, Alo, Bhi, Blo, c);
    epi_store_dense<EPI>(c, C, bias, N, bm0, bn0, pi, alpha);
}

// z-pair: z=0 -> EPI0 with (W0,b0); z=1 -> EPI1 with (W1,b1); out Cbase + z*ROW
template <int EPI0, int EPI1>
__global__ void __launch_bounds__(256, 2) tgemm_pair_k(
    const float* __restrict__ A, const float* __restrict__ W0,
    const float* __restrict__ b0, const float* __restrict__ W1,
    const float* __restrict__ b1, const float* __restrict__ pi,
    float* __restrict__ Cbase)
{
    __shared__ float Ahi[128][AS_STRIDE], Alo[128][AS_STRIDE];
    __shared__ float Bhi[16][BS_STRIDE], Blo[16][BS_STRIDE];
    const int z = blockIdx.z;
    const float* B = z ? W1 : W0;
    const float* bias = z ? b1 : b0;
    float* C = Cbase + (long)z * ROW;
    const int bm0 = blockIdx.y * 128, bn0 = blockIdx.x * 128;
    float c[2][8][4];
#pragma unroll
    for (int a = 0; a < 2; a++)
#pragma unroll
        for (int b = 0; b < 8; b++)
#pragma unroll
            for (int r = 0; r < 4; r++) c[a][b][r] = 0.f;
    tf32_loop<false, false>(A, B, D, D, bm0, bn0, nullptr, Ahi, Alo, Bhi, Blo, c);
    if (z == 0) epi_store_dense<EPI0>(c, C, bias, D, bm0, bn0, pi, 1.f);
    else        epi_store_dense<EPI1>(c, C, bias, D, bm0, bn0, pi, 1.f);
}

__global__ void __launch_bounds__(256, 2) tqkv_k(
    const float* __restrict__ A, const float* __restrict__ Wq,
    const float* __restrict__ Wk, const float* __restrict__ Wv,
    float* __restrict__ Cbase)
{
    __shared__ float Ahi[128][AS_STRIDE], Alo[128][AS_STRIDE];
    __shared__ float Bhi[16][BS_STRIDE], Blo[16][BS_STRIDE];
    const int z = blockIdx.z;
    const float* B = (z == 0) ? Wq : (z == 1) ? Wk : Wv;
    float* C = Cbase + (long)z * ROW;
    const int bm0 = blockIdx.y * 128, bn0 = blockIdx.x * 128;
    float c[2][8][4];
#pragma unroll
    for (int a = 0; a < 2; a++)
#pragma unroll
        for (int b = 0; b < 8; b++)
#pragma unroll
            for (int r = 0; r < 4; r++) c[a][b][r] = 0.f;
    tf32_loop<false, false>(A, B, D, D, bm0, bn0, nullptr, Ahi, Alo, Bhi, Blo, c);
    epi_store_dense<EPI_NONE>(c, C, nullptr, D, bm0, bn0, nullptr, 1.f);
}

// bank1: gathered A rows, gelu, bounded store by slot
__global__ void __launch_bounds__(256, 2) tbank1_k(
    const float* __restrict__ A, const float* __restrict__ W1all,
    const float* __restrict__ b1all, float* __restrict__ hb,
    const int* __restrict__ list, const int* __restrict__ cnt)
{
    const int s = blockIdx.z;
    const int cn = cnt[s];
    const int bm0 = blockIdx.y * 128;
    if (bm0 >= cn) return;
    __shared__ float Ahi[128][AS_STRIDE], Alo[128][AS_STRIDE];
    __shared__ float Bhi[16][BS_STRIDE], Blo[16][BS_STRIDE];
    __shared__ int rowTok[128];
    const int tid = threadIdx.x;
    if (tid < 128) rowTok[tid] = list[s * NTOK + min(bm0 + tid, cn - 1)];
    __syncthreads();

    const float* B = W1all + (long)s * D * FFN;
    const float* bias = b1all + s * FFN;
    float* C = hb + (long)s * NTOK * FFN;
    const int bn0 = blockIdx.x * 128;

    float c[2][8][4];
#pragma unroll
    for (int a = 0; a < 2; a++)
#pragma unroll
        for (int b = 0; b < 8; b++)
#pragma unroll
            for (int r = 0; r < 4; r++) c[a][b][r] = 0.f;
    tf32_loop<false, true>(A, B, D, FFN, 0, bn0, rowTok, Ahi, Alo, Bhi, Blo, c);

    const int lane = tid & 31, warp = tid >> 5;
    const int wm0 = (warp >> 1) * 32, wn0 = (warp & 1) * 64;
    const int g = lane >> 2, tig = lane & 3;
    const int colbase = bn0 + wn0;
#pragma unroll
    for (int mt = 0; mt < 2; mt++) {
#pragma unroll
        for (int half = 0; half < 2; half++) {
            int slot = bm0 + wm0 + mt * 16 + g + half * 8;
            if (slot >= cn) continue;
            float* cp = C + (long)slot * FFN + colbase;
#pragma unroll
            for (int nt = 0; nt < 8; nt++) {
                int col = nt * 8 + tig * 2;
                float v0 = gelu_f(c[mt][nt][half * 2] + bias[colbase + col]);
                float v1 = gelu_f(c[mt][nt][half * 2 + 1] + bias[colbase + col + 1]);
                *(float2*)(cp + col) = make_float2(v0, v1);
            }
        }
    }
}

// bank2: gathered hb slots, scatter to so[tok] (RANK0 assign / RANK1 accum)
template <int RANK>
__global__ void __launch_bounds__(256, 2) tbank2_k(
    const float* __restrict__ hb, const float* __restrict__ W2all,
    const float* __restrict__ b2all, float* __restrict__ so,
    const int* __restrict__ cnt2, const int* __restrict__ slot2,
    const int* __restrict__ tok2, const float* __restrict__ pi)
{
    const int s = blockIdx.z;
    const int cn = cnt2[RANK * NS + s];
    const int bm0 = blockIdx.y * 128;
    if (bm0 >= cn) return;
    __shared__ float Ahi[128][AS_STRIDE], Alo[128][AS_STRIDE];
    __shared__ float Bhi[16][BS_STRIDE], Blo[16][BS_STRIDE];
    __shared__ int rowSlot[128];
    const int tid = threadIdx.x;
    const int lbase = (RANK * NS + s) * NTOK;
    if (tid < 128) rowSlot[tid] = slot2[lbase + min(bm0 + tid, cn - 1)];
    __syncthreads();

    const float* A = hb + (long)s * NTOK * FFN;
    const float* B = W2all + (long)s * FFN * D;
    const float* bias = b2all + s * D;
    const int bn0 = blockIdx.x * 128;

    float c[2][8][4];
#pragma unroll
    for (int a = 0; a < 2; a++)
#pragma unroll
        for (int b = 0; b < 8; b++)
#pragma unroll
            for (int r = 0; r < 4; r++) c[a][b][r] = 0.f;
    tf32_loop<false, true>(A, B, FFN, D, 0, bn0, rowSlot, Ahi, Alo, Bhi, Blo, c);

    const int lane = tid & 31, warp = tid >> 5;
    const int wm0 = (warp >> 1) * 32, wn0 = (warp & 1) * 64;
    const int g = lane >> 2, tig = lane & 3;
    const int colbase = bn0 + wn0;
#pragma unroll
    for (int mt = 0; mt < 2; mt++) {
#pragma unroll
        for (int half = 0; half < 2; half++) {
            int idx = bm0 + wm0 + mt * 16 + g + half * 8;
            if (idx >= cn) continue;
            int tok = tok2[lbase + idx];
            float rs = pi[tok * NS + s];
            float* cp = so + (long)tok * D + colbase;
#pragma unroll
            for (int nt = 0; nt < 8; nt++) {
                int col = nt * 8 + tig * 2;
                float v0 = rs * (c[mt][nt][half * 2] + bias[colbase + col]);
                float v1 = rs * (c[mt][nt][half * 2 + 1] + bias[colbase + col + 1]);
                if (RANK == 0) {
                    *(float2*)(cp + col) = make_float2(v0, v1);
                } else {
                    float2 old = *(float2*)(cp + col);
                    *(float2*)(cp + col) = make_float2(old.x + v0, old.y + v1);
                }
            }
        }
    }
}

// ---------------- small kernels ----------------
__global__ void emb_k(const int* __restrict__ x, const float* __restrict__ emb,
                      const float* __restrict__ pos, float* __restrict__ h)
{
    int n = blockIdx.x;
    int vx = x[n];
    int t = n % TSEQ;
    const float* e = emb + (long)vx * D;
    const float* p = pos + (long)t * D;
    for (int j = threadIdx.x; j < D; j += blockDim.x)
        h[(long)n * D + j] = e[j] + p[j];
}

__global__ void pi_init_k(float* __restrict__ pi)
{
    int i = blockIdx.x * blockDim.x + threadIdx.x;
    if (i < NTOK * NS) pi[i] = ((i % NS) == 2) ? 1.f : 0.f;
}

__global__ void reset_cnt_k(int* cnt, int* cnt2)
{
    if (threadIdx.x < NS) cnt[threadIdx.x] = 0;
    if (threadIdx.x < 2 * NS) cnt2[threadIdx.x] = 0;
}

__global__ void build_lists_k(const float* __restrict__ pi,
                              int* __restrict__ cnt, int* __restrict__ list,
                              int* __restrict__ cnt2, int* __restrict__ slot2,
                              int* __restrict__ tok2)
{
    int t = blockIdx.x * blockDim.x + threadIdx.x;
    if (t >= NTOK) return;
    int r = 0;
#pragma unroll
    for (int s = 0; s < NS; s++) {
        if (pi[t * NS + s] != 0.f) {
            int p = atomicAdd(&cnt[s], 1);
            list[s * NTOK + p] = t;
            int rr = min(r, 1);
            int q = atomicAdd(&cnt2[rr * NS + s], 1);
            slot2[(rr * NS + s) * NTOK + q] = p;
            tok2[(rr * NS + s) * NTOK + q] = t;
            r++;
        }
    }
}

__global__ void ln012_k(const float* __restrict__ mu, float* __restrict__ muhat,
                        float* __restrict__ mun, float* __restrict__ mur,
                        const float* __restrict__ ln_g, const float* __restrict__ ln_b)
{
    __shared__ float red[8];
    int n = blockIdx.x, tid = threadIdx.x;
    const float* row = mu + (long)n * D;
    float v[3], s = 0.f;
#pragma unroll
    for (int r = 0; r < 3; r++) { v[r] = row[tid + r * 256]; s += v[r]; }
    float mean = block_sum(s, red) / D;
    float qv = 0.f;
#pragma unroll
    for (int r = 0; r < 3; r++) { float d = v[r] - mean; qv += d * d; }
    float var = block_sum(qv, red) / D;
    float inv = rsqrtf(var + 1e-5f);
#pragma unroll
    for (int r = 0; r < 3; r++) {
        int j = tid + r * 256;
        float nh = (v[r] - mean) * inv;
        long idx = (long)n * D + j;
        muhat[idx] = nh;
        mun[idx] = nh * ln_g[j] + ln_b[j];
        mur[idx] = nh * ln_g[2 * D + j] + ln_b[2 * D + j];
    }
}

__global__ void ln_gen_k(const float* __restrict__ in, float* __restrict__ out,
                         const float* __restrict__ g, const float* __restrict__ b)
{
    __shared__ float red[8];
    int n = blockIdx.x, tid = threadIdx.x;
    const float* row = in + (long)n * D;
    float v[3], s = 0.f;
#pragma unroll
    for (int r = 0; r < 3; r++) { v[r] = row[tid + r * 256]; s += v[r]; }
    float mean = block_sum(s, red) / D;
    float qv = 0.f;
#pragma unroll
    for (int r = 0; r < 3; r++) { float d = v[r] - mean; qv += d * d; }
    float var = block_sum(qv, red) / D;
    float inv = rsqrtf(var + 1e-5f);
#pragma unroll
    for (int r = 0; r < 3; r++) {
        int j = tid + r * 256;
        out[(long)n * D + j] = (v[r] - mean) * inv * g[j] + b[j];
    }
}

__global__ void routing_k(const float* __restrict__ trh, const float* __restrict__ w2,
                          const float* __restrict__ b2, const float* __restrict__ mun,
                          const float* __restrict__ evw, const float* __restrict__ evb,
                          float* __restrict__ pi)
{
    __shared__ float sh[1536];
    __shared__ float sm[D];
    __shared__ float kz[36];
    __shared__ float ev[6];
    __shared__ float spi[6];
    int n = blockIdx.x, tid = threadIdx.x;
    for (int i = tid; i < 1536; i += 128) sh[i] = trh[(long)n * 1536 + i];
    for (int i = tid; i < D; i += 128)    sm[i] = mun[(long)n * D + i];
    if (tid < NS) spi[tid] = pi[n * NS + tid];
    __syncthreads();
    if (tid < 36) {
        float acc = b2[tid];
        for (int k = 0; k < 1536; k++) acc += sh[k] * w2[k * 36 + tid];
        kz[tid] = acc;
    } else if (tid < 42) {
        int j = tid - 36;
        float acc = evb[j];
        for (int k = 0; k < D; k++) acc += sm[k] * evw[k * NS + j];
        ev[j] = acc;
    }
    __syncthreads();
    if (tid == 0) {
        float Kr[6][6];
        for (int s = 0; s < 6; s++) {
            float mx = kz[s * 6];
            for (int u = 1; u < 6; u++) mx = fmaxf(mx, kz[s * 6 + u]);
            float sum = 0.f;
            for (int u = 0; u < 6; u++) { float e = expf(kz[s * 6 + u] - mx); Kr[s][u] = e; sum += e; }
            float invr = 1.f / sum;
            for (int u = 0; u < 6; u++) Kr[s][u] *= invr;
        }
        float pev[6];
        for (int u = 0; u < 6; u++) {
            float a = 0.f;
            for (int s = 0; s < 6; s++) a += spi[s] * Kr[s][u];
            pev[u] = a;
        }
        float mx = ev[0] * 2.f;
        for (int u = 1; u < 6; u++) mx = fmaxf(mx, ev[u] * 2.f);
        float wv[6], sw = 0.f;
        for (int u = 0; u < 6; u++) { wv[u] = expf(ev[u] * 2.f - mx); sw += wv[u]; }
        float invw = 1.f / sw;
        float pn[6], s1 = 0.f;
        for (int u = 0; u < 6; u++) { pn[u] = pev[u] * wv[u] * invw; s1 += pn[u]; }
        float inv1 = 1.f / fmaxf(s1, 1e-8f);
        for (int u = 0; u < 6; u++) pn[u] *= inv1;
        int i1 = 0;
        for (int u = 1; u < 6; u++) if (pn[u] > pn[i1]) i1 = u;
        int i2 = (i1 == 0) ? 1 : 0;
        for (int u = 0; u < 6; u++) if (u != i1 && pn[u] > pn[i2]) i2 = u;
        float inv2 = 1.f / fmaxf(pn[i1] + pn[i2], 1e-8f);
        for (int u = 0; u < 6; u++)
            pi[n * NS + u] = (u == i1 || u == i2) ? pn[u] * inv2 : 0.f;
    }
}

__global__ void attn_k(const float* __restrict__ q, const float* __restrict__ k,
                       const float* __restrict__ v, const float* __restrict__ pi,
                       const float* __restrict__ ln_g, const float* __restrict__ ln_b,
                       float* __restrict__ msg)
{
    __shared__ float sw[4];
    __shared__ float mb[D];
    __shared__ float red[8];
    int n = blockIdx.x, tid = threadIdx.x;
    int t = n % TSEQ;
    int warp = tid >> 5, lane = tid & 31;
    const int offs[4] = {-2, -1, 1, 2};
    {
        int o = offs[warp];
        int tt = t + o;
        float dot = 0.f;
        if (tt >= 0 && tt < TSEQ) {
            const float* qp = q + (long)n * D;
            const float* kp = k + (long)(n + o) * D;
            for (int j = lane; j < D; j += 32) dot += qp[j] * kp[j];
        }
#pragma unroll
        for (int s = 16; s > 0; s >>= 1) dot += __shfl_xor_sync(0xffffffffu, dot, s);
        if (lane == 0)
            sw[warp] = (tt >= 0 && tt < TSEQ) ? dot / 27.712812921102035f : -1e9f;
    }
    __syncthreads();
    float w0 = sw[0], w1 = sw[1], w2 = sw[2], w3 = sw[3];
    float mx = fmaxf(fmaxf(w0, w1), fmaxf(w2, w3));
    float wt[4] = {expf(w0 - mx), expf(w1 - mx), expf(w2 - mx), expf(w3 - mx)};
    float invs = 1.f / (wt[0] + wt[1] + wt[2] + wt[3]);
#pragma unroll
    for (int w = 0; w < 4; w++) wt[w] *= invs;
    float pi3 = pi[n * NS + 3];
    for (int j = tid; j < D; j += 128) {
        float m = 0.f;
#pragma unroll
        for (int w = 0; w < 4; w++) {
            int tt = t + offs[w];
            if (tt >= 0 && tt < TSEQ) m += wt[w] * v[(long)(n + offs[w]) * D + j];
        }
        mb[j] = m * pi3;
    }
    __syncthreads();
    float loc[6], s = 0.f;
#pragma unroll
    for (int r = 0; r < 6; r++) { loc[r] = mb[tid + r * 128]; s += loc[r]; }
    float mean = block_sum(s, red) / D;
    float qv = 0.f;
#pragma unroll
    for (int r = 0; r < 6; r++) { float d = loc[r] - mean; qv += d * d; }
    float var = block_sum(qv, red) / D;
    float inv = rsqrtf(var + 1e-5f);
#pragma unroll
    for (int r = 0; r < 6; r++) {
        int j = tid + r * 128;
        msg[(long)n * D + j] = (loc[r] - mean) * inv * ln_g[3 * D + j] + ln_b[3 * D + j];
    }
}

__global__ void update_k(const float* __restrict__ muhat, float* __restrict__ lam,
                         const float* __restrict__ dlam, const float* __restrict__ mhat,
                         const float* __restrict__ so,
                         const float* __restrict__ ln_g, const float* __restrict__ ln_b,
                         float* __restrict__ mu)
{
    __shared__ float red[8];
    int n = blockIdx.x, tid = threadIdx.x;
    float mval[3], s = 0.f;
#pragma unroll
    for (int r = 0; r < 3; r++) {
        int j = tid + r * 256;
        long idx = (long)n * D + j;
        float l = lam[idx], dl = dlam[idx];
        float mwn = muhat[idx] * ln_g[4 * D + j] + ln_b[4 * D + j];
        float lnw = l + dl;
        float m = (l * mwn + dl * mhat[idx]) / lnw;
        lam[idx] = lnw;
        mval[r] = m;
        s += m;
    }
    float mean = block_sum(s, red) / D;
    float qv = 0.f;
#pragma unroll
    for (int r = 0; r < 3; r++) { float d = mval[r] - mean; qv += d * d; }
    float var = block_sum(qv, red) / D;
    float inv = rsqrtf(var + 1e-5f);
#pragma unroll
    for (int r = 0; r < 3; r++) {
        int j = tid + r * 256;
        long idx = (long)n * D + j;
        mu[idx] = (mval[r] - mean) * inv * ln_g[5 * D + j] + ln_b[5 * D + j] + so[idx] * 0.1f;
    }
}

// ---------------- launcher ----------------
extern "C" void kernel_launch(void* const* d_in, const int* in_sizes, int n_in,
                              void* d_out, int out_size)
{
    const int*   x        = (const int*)d_in[0];
    const float* emb_w    = (const float*)d_in[1];
    const float* pos_w    = (const float*)d_in[2];
    const float* mu_w     = (const float*)d_in[3];
    const float* mu_b     = (const float*)d_in[4];
    const float* lam_w    = (const float*)d_in[5];
    const float* lam_b    = (const float*)d_in[6];
    const float* tr_w1    = (const float*)d_in[7];
    const float* tr_b1    = (const float*)d_in[8];
    const float* tr_w2    = (const float*)d_in[9];
    const float* tr_b2    = (const float*)d_in[10];
    const float* bank_w1  = (const float*)d_in[11];
    const float* bank_b1  = (const float*)d_in[12];
    const float* bank_w2  = (const float*)d_in[13];
    const float* bank_b2  = (const float*)d_in[14];
    const float* ev_w     = (const float*)d_in[15];
    const float* ev_b     = (const float*)d_in[16];
    const float* rt_q     = (const float*)d_in[17];
    const float* rt_k     = (const float*)d_in[18];
    const float* rt_v     = (const float*)d_in[19];
    const float* wr_lam_w = (const float*)d_in[20];
    const float* wr_lam_b = (const float*)d_in[21];
    const float* wr_mu_w  = (const float*)d_in[22];
    const float* wr_mu_b  = (const float*)d_in[23];
    const float* ln_g     = (const float*)d_in[24];
    const float* ln_b     = (const float*)d_in[25];
    float* out = (float*)d_out;

    float* base = nullptr;
    cudaGetSymbolAddress((void**)&base, g_scratch);
    int *cnt, *list, *cnt2, *slot2, *tok2;
    cudaGetSymbolAddress((void**)&cnt, g_cnt);
    cudaGetSymbolAddress((void**)&list, g_list);
    cudaGetSymbolAddress((void**)&cnt2, g_cnt2);
    cudaGetSymbolAddress((void**)&slot2, g_slot2);
    cudaGetSymbolAddress((void**)&tok2, g_tok2);

    float* h     = base + OFF_H;
    float* mu    = base + OFF_MU;
    float* muhat = base + OFF_MUHAT;
    float* mun   = base + OFF_MUN;
    float* mur   = base + OFF_MUR;
    float* so    = base + OFF_SO;
    float* qb    = base + OFF_Q;
    float* lam   = base + OFF_LAM;
    float* msg   = base + OFF_MSG;
    float* dlam  = base + OFF_DLAM;
    float* mhat  = base + OFF_MHAT;
    float* fin   = base + OFF_FIN;
    float* trh   = base + OFF_TRH;
    float* hb    = base + OFF_HB;
    float* pi    = base + OFF_PI;

    const float inv_sqrt_d = 0.03608439182435161f;

    emb_k<<<NTOK, 256>>>(x, emb_w, pos_w, h);
    {
        dim3 g(D / 128, NTOK / 128, 2);
        tgemm_pair_k<EPI_BIAS, EPI_SP01><<<g, 256>>>(h, mu_w, mu_b, lam_w, lam_b,
                                                     nullptr, mu); // mu z=0, lam z=1
    }
    pi_init_k<<<(NTOK * NS + 255) / 256, 256>>>(pi);

    for (int step = 0; step < 3; step++) {
        ln012_k<<<NTOK, 256>>>(mu, muhat, mun, mur, ln_g, ln_b);
        {
            dim3 g(1536 / 128, NTOK / 128);
            tgemm_k<EPI_GELU, false><<<g, 256>>>(mu, tr_w1, tr_b1, trh, 1536, D, 1.f, nullptr);
        }
        reset_cnt_k<<<1, 32>>>(cnt, cnt2);
        build_lists_k<<<NTOK / 256, 256>>>(pi, cnt, list, cnt2, slot2, tok2);
        {
            dim3 g1(FFN / 128, NTOK / 128, NS);
            tbank1_k<<<g1, 256>>>(mun, bank_w1, bank_b1, hb, list, cnt);
            dim3 g2(D / 128, NTOK / 128, NS);
            tbank2_k<0><<<g2, 256>>>(hb, bank_w2, bank_b2, so, cnt2, slot2, tok2, pi);
            tbank2_k<1><<<g2, 256>>>(hb, bank_w2, bank_b2, so, cnt2, slot2, tok2, pi);
        }
        ln_gen_k<<<NTOK, 256>>>(so, so, ln_g + 1 * D, ln_b + 1 * D);
        routing_k<<<NTOK, 128>>>(trh, tr_w2, tr_b2, mun, ev_w, ev_b, pi);
        {
            dim3 g(D / 128, NTOK / 128, 3);
            tqkv_k<<<g, 256>>>(mur, rt_q, rt_k, rt_v, qb);
        }
        attn_k<<<NTOK, 128>>>(qb, qb + ROW, qb + 2 * ROW, pi, ln_g, ln_b, msg);
        {
            dim3 g(D / 128, NTOK / 128, 2);
            tgemm_pair_k<EPI_GSP, EPI_BIAS><<<g, 256>>>(msg, wr_lam_w, wr_lam_b,
                                                        wr_mu_w, wr_mu_b, pi, dlam);
        }
        update_k<<<NTOK, 256>>>(muhat, lam, dlam, mhat, so, ln_g, ln_b, mu);
    }

    ln_gen_k<<<NTOK, 256>>>(mu, fin, ln_g + 6 * D, ln_b + 6 * D);
    {
        dim3 g(VOC / 128, NTOK / 128);
        tgemm_k<EPI_SCALE, true><<<g, 256>>>(fin, emb_w, nullptr, out, VOC, D,
                                             inv_sqrt_d, nullptr);
    }
}